// round 5
// baseline (speedup 1.0000x reference)
#include <cuda_runtime.h>
#include <cuda_bf16.h>
#include <cstdint>

#define T_DIM 2048
#define H_DIM 2048
#define NHEAD 16
#define HDIM 128
#define QKV_N (3 * H_DIM)
#define EPS_V 1e-6f
#define SCALE_V 0.08838834764831845f   // 128^-0.5
#define LOG_THETA 13.122363377404328f  // ln(500000)

// Scratch (device globals — no runtime allocation allowed)
__device__ float g_qkv[(size_t)T_DIM * QKV_N];   // 48 MB: [q | k | v] per row
__device__ float g_attn[(size_t)T_DIM * H_DIM];  // 16 MB

__device__ __forceinline__ uint32_t smem_u32(const void* p) {
    uint32_t a;
    asm("{ .reg .u64 t; cvta.to.shared.u64 t, %1; cvt.u32.u64 %0, t; }" : "=r"(a) : "l"(p));
    return a;
}
#define SWZ(o) ((o) ^ (((o) >> 3) & 0x70))

__device__ __forceinline__ void ldsm4(uint32_t& r0, uint32_t& r1, uint32_t& r2,
                                      uint32_t& r3, uint32_t addr) {
    asm volatile("ldmatrix.sync.aligned.m8n8.x4.shared.b16 {%0,%1,%2,%3}, [%4];"
                 : "=r"(r0), "=r"(r1), "=r"(r2), "=r"(r3) : "r"(addr));
}
__device__ __forceinline__ void mma_bf16(float* c, const uint32_t* a, uint32_t b0,
                                         uint32_t b1) {
    asm volatile(
        "mma.sync.aligned.m16n8k16.row.col.f32.bf16.bf16.f32 "
        "{%0,%1,%2,%3}, {%4,%5,%6,%7}, {%8,%9}, {%0,%1,%2,%3};"
        : "+f"(c[0]), "+f"(c[1]), "+f"(c[2]), "+f"(c[3])
        : "r"(a[0]), "r"(a[1]), "r"(a[2]), "r"(a[3]), "r"(b0), "r"(b1));
}

// ===========================================================================
// Tensor-core GEMM via ldmatrix + mma.sync (bf16 3-way split, fp32 accum).
// C[M,N] = A[M,K] @ B[K,N]. 128x128 CTA tile, BK=64, 256 threads.
// smem: A_hi 16K | A_lo 16K | B_hi 16K | B_lo 16K (dynamic, 64 KB)
// ===========================================================================
#define GOFF_AHI 0
#define GOFF_ALO 16384
#define GOFF_BHI 32768
#define GOFF_BLO 49152
#define GSMEM_BYTES 65536

__global__ __launch_bounds__(256) void gemm_mma(const float* __restrict__ A,
                                                const float* __restrict__ B,
                                                float* __restrict__ C,
                                                int M, int N, int K) {
    extern __shared__ char sm[];
    const uint32_t sb = smem_u32(sm);
    const int tid = threadIdx.x;
    const int warp = tid >> 5, lane = tid & 31;
    const int row0 = blockIdx.y * 128;
    const int col0 = blockIdx.x * 128;

    // Warp tile: 64 m x 32 n. 2 warps along m, 4 along n.
    const int wm0 = (warp & 1) * 64;
    const int wn0 = (warp >> 1) * 32;

    // ldmatrix lane address components
    const int a_rif = lane & 15;               // row within m16 frag
    const int a_kb = (lane >> 4) * 16;         // byte col: 0 or 16
    const int b_nrow = (lane & 7) + ((lane >> 4) & 1) * 8;
    const int b_kb = ((lane >> 3) & 1) * 16;

    // gmem->smem fill mappings (same as R3 layout)
    const int a_k4 = tid & 15;
    const int a_mr = tid >> 4;
    const int b_i = lane >> 2;
    const int b_j = lane & 3;

    float c[4][4][4];
#pragma unroll
    for (int mf = 0; mf < 4; mf++)
#pragma unroll
        for (int nf = 0; nf < 4; nf++)
#pragma unroll
            for (int i = 0; i < 4; i++) c[mf][nf][i] = 0.0f;

    const int nchunks = K >> 6;
    for (int kc = 0; kc < nchunks; kc++) {
        const int kbase = kc << 6;
        __syncthreads();

        // ---- A tile: [128 m][64 k] fp32 -> bf16 hi/lo, SW128 swizzled ----
#pragma unroll
        for (int r = 0; r < 8; r++) {
            const int m = r * 16 + a_mr;
            float4 a = *(const float4*)(A + (size_t)(row0 + m) * K + kbase + a_k4 * 4);
            __nv_bfloat162 h01 = __floats2bfloat162_rn(a.x, a.y);
            __nv_bfloat162 h23 = __floats2bfloat162_rn(a.z, a.w);
            __nv_bfloat162 l01 = __floats2bfloat162_rn(a.x - __bfloat162float(h01.x),
                                                       a.y - __bfloat162float(h01.y));
            __nv_bfloat162 l23 = __floats2bfloat162_rn(a.z - __bfloat162float(h23.x),
                                                       a.w - __bfloat162float(h23.y));
            const uint32_t off = SWZ((uint32_t)(m * 128 + a_k4 * 8));
            *(uint2*)(sm + GOFF_AHI + off) = make_uint2(*(uint32_t*)&h01, *(uint32_t*)&h23);
            *(uint2*)(sm + GOFF_ALO + off) = make_uint2(*(uint32_t*)&l01, *(uint32_t*)&l23);
        }

        // ---- B tile transposed: Bs[n][k] = B[kbase+k][col0+n] ----
#pragma unroll
        for (int ns = 0; ns < 2; ns++) {
            const int n = warp * 16 + ns * 8 + b_i;
            const float* bp = B + (size_t)kbase * N + col0 + n;
#pragma unroll
            for (int k0 = 0; k0 < 64; k0 += 8) {
                const int k = k0 + 2 * b_j;
                float x0 = bp[(size_t)k * N];
                float x1 = bp[(size_t)(k + 1) * N];
                __nv_bfloat162 h = __floats2bfloat162_rn(x0, x1);
                __nv_bfloat162 l = __floats2bfloat162_rn(x0 - __bfloat162float(h.x),
                                                         x1 - __bfloat162float(h.y));
                const uint32_t off = SWZ((uint32_t)(n * 128 + k * 2));
                *(uint32_t*)(sm + GOFF_BHI + off) = *(uint32_t*)&h;
                *(uint32_t*)(sm + GOFF_BLO + off) = *(uint32_t*)&l;
            }
        }
        __syncthreads();

        // ---- 4 k16 steps: ldmatrix frags + 3-pass mma ----
#pragma unroll
        for (int ks = 0; ks < 4; ks++) {
            uint32_t ah[4][4], al[4][4], bh[2][4], bl[2][4];
#pragma unroll
            for (int mf = 0; mf < 4; mf++) {
                const uint32_t lo = SWZ((uint32_t)((wm0 + mf * 16 + a_rif) * 128 + ks * 32 + a_kb));
                ldsm4(ah[mf][0], ah[mf][1], ah[mf][2], ah[mf][3], sb + GOFF_AHI + lo);
                ldsm4(al[mf][0], al[mf][1], al[mf][2], al[mf][3], sb + GOFF_ALO + lo);
            }
#pragma unroll
            for (int nf2 = 0; nf2 < 2; nf2++) {
                const uint32_t lo = SWZ((uint32_t)((wn0 + nf2 * 16 + b_nrow) * 128 + ks * 32 + b_kb));
                ldsm4(bh[nf2][0], bh[nf2][1], bh[nf2][2], bh[nf2][3], sb + GOFF_BHI + lo);
                ldsm4(bl[nf2][0], bl[nf2][1], bl[nf2][2], bl[nf2][3], sb + GOFF_BLO + lo);
            }
#pragma unroll
            for (int mf = 0; mf < 4; mf++)
#pragma unroll
                for (int nf = 0; nf < 4; nf++) {
                    const int g = nf >> 1, h2 = (nf & 1) * 2;
                    mma_bf16(c[mf][nf], ah[mf], bh[g][h2], bh[g][h2 + 1]);
                    mma_bf16(c[mf][nf], al[mf], bh[g][h2], bh[g][h2 + 1]);
                    mma_bf16(c[mf][nf], ah[mf], bl[g][h2], bl[g][h2 + 1]);
                }
        }
    }

    // ---- Epilogue: frags -> C ----
    const int erow = (lane >> 2);
    const int ecol = (lane & 3) * 2;
#pragma unroll
    for (int mf = 0; mf < 4; mf++) {
        const int row = row0 + wm0 + mf * 16 + erow;
#pragma unroll
        for (int nf = 0; nf < 4; nf++) {
            const int col = col0 + wn0 + nf * 8 + ecol;
            *(float2*)(C + (size_t)row * N + col) = make_float2(c[mf][nf][0], c[mf][nf][1]);
            *(float2*)(C + (size_t)(row + 8) * N + col) = make_float2(c[mf][nf][2], c[mf][nf][3]);
        }
    }
}

// ---------------------------------------------------------------------------
// Fused RMSNorm (over full H=2048 for q and k) + RoPE, in-place on g_qkv.
// ---------------------------------------------------------------------------
__global__ void rmsnorm_rope_kernel(const int* __restrict__ positions,
                                    const float* __restrict__ qw,
                                    const float* __restrict__ kw) {
    const int t = blockIdx.x;
    float* q = g_qkv + (size_t)t * QKV_N;
    float* k = q + H_DIM;

    __shared__ float sh[32];
    const int lane = threadIdx.x & 31, warp = threadIdx.x >> 5;

    float sq = 0.0f, sk = 0.0f;
    for (int i = threadIdx.x; i < H_DIM; i += 256) {
        float a = q[i]; sq += a * a;
        float b = k[i]; sk += b * b;
    }
#pragma unroll
    for (int o = 16; o; o >>= 1) sq += __shfl_xor_sync(~0u, sq, o);
    if (lane == 0) sh[warp] = sq;
    __syncthreads();
    if (threadIdx.x < 32) {
        float v = (threadIdx.x < 8) ? sh[threadIdx.x] : 0.0f;
#pragma unroll
        for (int o = 4; o; o >>= 1) v += __shfl_xor_sync(~0u, v, o);
        if (threadIdx.x == 0) sh[0] = v;
    }
    __syncthreads();
    const float invq = rsqrtf(sh[0] / (float)H_DIM + EPS_V);
    __syncthreads();
#pragma unroll
    for (int o = 16; o; o >>= 1) sk += __shfl_xor_sync(~0u, sk, o);
    if (lane == 0) sh[warp] = sk;
    __syncthreads();
    if (threadIdx.x < 32) {
        float v = (threadIdx.x < 8) ? sh[threadIdx.x] : 0.0f;
#pragma unroll
        for (int o = 4; o; o >>= 1) v += __shfl_xor_sync(~0u, v, o);
        if (threadIdx.x == 0) sh[0] = v;
    }
    __syncthreads();
    const float invk = rsqrtf(sh[0] / (float)H_DIM + EPS_V);
    __syncthreads();

    const float p = (float)positions[t];
    for (int idx = threadIdx.x; idx < NHEAD * (HDIM / 2); idx += 256) {
        const int h = idx >> 6;
        const int d = idx & 63;
        const int i1 = h * HDIM + d;
        const int i2 = i1 + (HDIM / 2);
        const float fr = p * __expf(-LOG_THETA * (float)d * (1.0f / 64.0f));
        float cc, ss;
        __sincosf(fr, &ss, &cc);

        float q1 = q[i1] * invq * qw[i1];
        float q2 = q[i2] * invq * qw[i2];
        q[i1] = q1 * cc - q2 * ss;
        q[i2] = q2 * cc + q1 * ss;

        float k1 = k[i1] * invk * kw[i1];
        float k2 = k[i2] * invk * kw[i2];
        k[i1] = k1 * cc - k2 * ss;
        k[i2] = k2 * cc + k1 * ss;
    }
}

// ---------------------------------------------------------------------------
// Flash attention (fp32): one block per (head, 64-q-row tile). 256 threads.
// ---------------------------------------------------------------------------
#define QT 64
#define KT 64
#define KPAD (HDIM + 4)
#define SM_QS 0
#define SM_KS (SM_QS + QT * HDIM)
#define SM_VS (SM_KS + KT * KPAD)
#define SM_PS (SM_VS + KT * HDIM)
#define SM_FLOATS (SM_PS + QT * KT)
#define SM_BYTES (SM_FLOATS * 4)

__global__ void flash_attn() {
    extern __shared__ float smf[];
    float* Qs = smf + SM_QS;
    float* Ks = smf + SM_KS;
    float* Vs = smf + SM_VS;
    float* Ps = smf + SM_PS;

    const int h = blockIdx.y;
    const int qt = gridDim.x - 1 - blockIdx.x;  // heavy tiles first
    const int q0 = qt * QT;
    const int tid = threadIdx.x;
    const int warp = tid >> 5, lane = tid & 31;

    for (int i = tid; i < QT * (HDIM / 4); i += 256) {
        int q = i >> 5;
        int d4 = (i & 31) * 4;
        float4 v = *(const float4*)(g_qkv + (size_t)(q0 + q) * QKV_N + h * HDIM + d4);
        v.x *= SCALE_V; v.y *= SCALE_V; v.z *= SCALE_V; v.w *= SCALE_V;
        *(float4*)&Qs[q * HDIM + d4] = v;
    }

    float m[8], l[8], acc[8][4];
#pragma unroll
    for (int i = 0; i < 8; i++) {
        m[i] = -1e30f; l[i] = 0.0f;
#pragma unroll
        for (int j = 0; j < 4; j++) acc[i][j] = 0.0f;
    }

    const int ntiles = qt + 1;
    for (int t = 0; t < ntiles; t++) {
        const int k0 = t * KT;
        __syncthreads();
        for (int i = tid; i < KT * (HDIM / 4); i += 256) {
            int k = i >> 5;
            int d4 = (i & 31) * 4;
            const float* base = g_qkv + (size_t)(k0 + k) * QKV_N + h * HDIM + d4;
            *(float4*)&Ks[k * KPAD + d4] = *(const float4*)(base + H_DIM);
            *(float4*)&Vs[k * HDIM + d4] = *(const float4*)(base + 2 * H_DIM);
        }
        __syncthreads();

        float s[8][2];
#pragma unroll
        for (int qi = 0; qi < 8; qi++) { s[qi][0] = 0.0f; s[qi][1] = 0.0f; }

        const float* k0p = Ks + lane * KPAD;
        const float* k1p = Ks + (lane + 32) * KPAD;
#pragma unroll 4
        for (int d = 0; d < HDIM; d += 4) {
            float4 ka = *(const float4*)(k0p + d);
            float4 kb = *(const float4*)(k1p + d);
#pragma unroll
            for (int qi = 0; qi < 8; qi++) {
                float4 qv = *(const float4*)&Qs[(warp * 8 + qi) * HDIM + d];
                s[qi][0] += qv.x * ka.x + qv.y * ka.y + qv.z * ka.z + qv.w * ka.w;
                s[qi][1] += qv.x * kb.x + qv.y * kb.y + qv.z * kb.z + qv.w * kb.w;
            }
        }

        if (t == qt) {
#pragma unroll
            for (int qi = 0; qi < 8; qi++) {
                int qloc = warp * 8 + qi;
                if (lane > qloc) s[qi][0] = -1e30f;
                if (lane + 32 > qloc) s[qi][1] = -1e30f;
            }
        }

#pragma unroll
        for (int qi = 0; qi < 8; qi++) {
            float mt = fmaxf(s[qi][0], s[qi][1]);
#pragma unroll
            for (int o = 16; o; o >>= 1) mt = fmaxf(mt, __shfl_xor_sync(~0u, mt, o));
            float mnew = fmaxf(m[qi], mt);
            float corr = __expf(m[qi] - mnew);
            float p0 = __expf(s[qi][0] - mnew);
            float p1 = __expf(s[qi][1] - mnew);
            float ps = p0 + p1;
#pragma unroll
            for (int o = 16; o; o >>= 1) ps += __shfl_xor_sync(~0u, ps, o);
            l[qi] = l[qi] * corr + ps;
            m[qi] = mnew;
#pragma unroll
            for (int j = 0; j < 4; j++) acc[qi][j] *= corr;
            Ps[(warp * 8 + qi) * KT + lane] = p0;
            Ps[(warp * 8 + qi) * KT + lane + 32] = p1;
        }
        __syncwarp();

#pragma unroll 4
        for (int kk = 0; kk < KT; kk += 2) {
            float4 v0 = *(const float4*)&Vs[kk * HDIM + lane * 4];
            float4 v1 = *(const float4*)&Vs[(kk + 1) * HDIM + lane * 4];
#pragma unroll
            for (int qi = 0; qi < 8; qi++) {
                float2 p = *(const float2*)&Ps[(warp * 8 + qi) * KT + kk];
                acc[qi][0] += p.x * v0.x + p.y * v1.x;
                acc[qi][1] += p.x * v0.y + p.y * v1.y;
                acc[qi][2] += p.x * v0.z + p.y * v1.z;
                acc[qi][3] += p.x * v0.w + p.y * v1.w;
            }
        }
    }

#pragma unroll
    for (int qi = 0; qi < 8; qi++) {
        float inv = 1.0f / l[qi];
        float4 o = make_float4(acc[qi][0] * inv, acc[qi][1] * inv,
                               acc[qi][2] * inv, acc[qi][3] * inv);
        *(float4*)(g_attn + (size_t)(q0 + warp * 8 + qi) * H_DIM + h * HDIM + lane * 4) = o;
    }
}

// ---------------------------------------------------------------------------
extern "C" void kernel_launch(void* const* d_in, const int* in_sizes, int n_in,
                              void* d_out, int out_size) {
    const int* positions = (const int*)d_in[0];
    const float* hidden = (const float*)d_in[1];
    const float* w_qkv = (const float*)d_in[2];
    const float* q_norm_w = (const float*)d_in[3];
    const float* k_norm_w = (const float*)d_in[4];
    const float* w_o = (const float*)d_in[5];
    float* out = (float*)d_out;

    void* p_qkv = nullptr;
    void* p_attn = nullptr;
    cudaGetSymbolAddress(&p_qkv, g_qkv);
    cudaGetSymbolAddress(&p_attn, g_attn);

    cudaFuncSetAttribute(gemm_mma, cudaFuncAttributeMaxDynamicSharedMemorySize, GSMEM_BYTES);
    cudaFuncSetAttribute(flash_attn, cudaFuncAttributeMaxDynamicSharedMemorySize, SM_BYTES);

    // 1) QKV projection: [T, H] @ [H, 3H]  (bf16 3-way split mma.sync)
    {
        dim3 grid(QKV_N / 128, T_DIM / 128);
        gemm_mma<<<grid, 256, GSMEM_BYTES>>>(hidden, w_qkv, (float*)p_qkv, T_DIM, QKV_N, H_DIM);
    }
    // 2) RMSNorm + RoPE in-place on q,k
    rmsnorm_rope_kernel<<<T_DIM, 256>>>(positions, q_norm_w, k_norm_w);
    // 3) Causal flash attention
    {
        dim3 grid(T_DIM / QT, NHEAD);
        flash_attn<<<grid, 256, SM_BYTES>>>();
    }
    // 4) Output projection: [T, H] @ [H, H]
    {
        dim3 grid(H_DIM / 128, T_DIM / 128);
        gemm_mma<<<grid, 256, GSMEM_BYTES>>>((const float*)p_attn, w_o, out, T_DIM, H_DIM, H_DIM);
    }
}

// round 9
// speedup vs baseline: 1.8634x; 1.8634x over previous
#include <cuda_runtime.h>
#include <cuda_bf16.h>
#include <cstdint>

#define T_DIM 2048
#define H_DIM 2048
#define NHEAD 16
#define HDIM 128
#define QKV_N (3 * H_DIM)
#define EPS_V 1e-6f
#define SCALE_V 0.08838834764831845f   // 128^-0.5
#define LOG_THETA 13.122363377404328f  // ln(500000)

// Scratch (device globals — no runtime allocation allowed)
__device__ __align__(128) float g_qkv[(size_t)T_DIM * QKV_N];   // 48 MB
__device__ __align__(128) float g_attn[(size_t)T_DIM * H_DIM];  // 16 MB
// bf16 hi/lo split operands
__device__ __align__(128) __nv_bfloat16 g_hid_hi[(size_t)T_DIM * H_DIM];
__device__ __align__(128) __nv_bfloat16 g_hid_lo[(size_t)T_DIM * H_DIM];
__device__ __align__(128) __nv_bfloat16 g_wqkv_hi[(size_t)QKV_N * H_DIM];  // [N][K]
__device__ __align__(128) __nv_bfloat16 g_wqkv_lo[(size_t)QKV_N * H_DIM];
__device__ __align__(128) __nv_bfloat16 g_wo_hi[(size_t)H_DIM * H_DIM];    // [N][K]
__device__ __align__(128) __nv_bfloat16 g_wo_lo[(size_t)H_DIM * H_DIM];
__device__ __align__(128) __nv_bfloat16 g_at_hi[(size_t)T_DIM * H_DIM];
__device__ __align__(128) __nv_bfloat16 g_at_lo[(size_t)T_DIM * H_DIM];

__device__ __forceinline__ uint32_t smem_u32(const void* p) {
    uint32_t a;
    asm("{ .reg .u64 t; cvta.to.shared.u64 t, %1; cvt.u32.u64 %0, t; }" : "=r"(a) : "l"(p));
    return a;
}
#define SWZ(o) ((o) ^ (((o) >> 3) & 0x70))

__device__ __forceinline__ void ldsm4(uint32_t& r0, uint32_t& r1, uint32_t& r2,
                                      uint32_t& r3, uint32_t addr) {
    asm volatile("ldmatrix.sync.aligned.m8n8.x4.shared.b16 {%0,%1,%2,%3}, [%4];"
                 : "=r"(r0), "=r"(r1), "=r"(r2), "=r"(r3) : "r"(addr));
}
__device__ __forceinline__ void mma_bf16(float* c, const uint32_t* a, uint32_t b0,
                                         uint32_t b1) {
    asm volatile(
        "mma.sync.aligned.m16n8k16.row.col.f32.bf16.bf16.f32 "
        "{%0,%1,%2,%3}, {%4,%5,%6,%7}, {%8,%9}, {%0,%1,%2,%3};"
        : "+f"(c[0]), "+f"(c[1]), "+f"(c[2]), "+f"(c[3])
        : "r"(a[0]), "r"(a[1]), "r"(a[2]), "r"(a[3]), "r"(b0), "r"(b1));
}
__device__ __forceinline__ void cpa16(uint32_t dst, const void* src) {
    asm volatile("cp.async.cg.shared.global [%0], [%1], 16;" :: "r"(dst), "l"(src));
}
#define CP_COMMIT() asm volatile("cp.async.commit_group;" ::: "memory")
#define CP_WAIT(n)  asm volatile("cp.async.wait_group %0;" :: "n"(n) : "memory")

// ===========================================================================
// Converters: fp32 -> bf16 hi + bf16 lo (residual)
// ===========================================================================
__global__ void convert_nt(const float* __restrict__ src, __nv_bfloat16* __restrict__ hi,
                           __nv_bfloat16* __restrict__ lo, int n4) {
    int i = blockIdx.x * blockDim.x + threadIdx.x;
    if (i >= n4) return;
    float4 v = *(const float4*)(src + (size_t)i * 4);
    __nv_bfloat162 h01 = __floats2bfloat162_rn(v.x, v.y);
    __nv_bfloat162 h23 = __floats2bfloat162_rn(v.z, v.w);
    __nv_bfloat162 l01 = __floats2bfloat162_rn(v.x - __bfloat162float(h01.x),
                                               v.y - __bfloat162float(h01.y));
    __nv_bfloat162 l23 = __floats2bfloat162_rn(v.z - __bfloat162float(h23.x),
                                               v.w - __bfloat162float(h23.y));
    *(uint2*)(hi + (size_t)i * 4) = make_uint2(*(uint32_t*)&h01, *(uint32_t*)&h23);
    *(uint2*)(lo + (size_t)i * 4) = make_uint2(*(uint32_t*)&l01, *(uint32_t*)&l23);
}

// Transposing converter: src [R][C] fp32 -> dst [C][R] bf16 hi/lo
__global__ void convert_t(const float* __restrict__ src, __nv_bfloat16* __restrict__ hi,
                          __nv_bfloat16* __restrict__ lo, int R, int C) {
    __shared__ float tile[32][33];
    const int bx = blockIdx.x * 32;  // C offset
    const int by = blockIdx.y * 32;  // R offset
    const int x = threadIdx.x;
#pragma unroll
    for (int y = threadIdx.y; y < 32; y += 8)
        tile[y][x] = src[(size_t)(by + y) * C + bx + x];
    __syncthreads();
#pragma unroll
    for (int y = threadIdx.y; y < 32; y += 8) {
        float v = tile[x][y];
        __nv_bfloat16 h = __float2bfloat16(v);
        __nv_bfloat16 l = __float2bfloat16(v - __bfloat162float(h));
        hi[(size_t)(bx + y) * R + by + x] = h;
        lo[(size_t)(bx + y) * R + by + x] = l;
    }
}

// ===========================================================================
// bf16 3-pass GEMM: C[M,N] = A[M,K] @ B^T where A hi/lo [M][K], B hi/lo [N][K].
// 128x128 CTA tile, BK=64, 256 threads, cp.async 2-stage double buffer.
// Stage layout (64 KB): AHI 0 | ALO 16K | BHI 32K | BLO 48K; 2 stages = 128 KB.
// ===========================================================================
#define STG 65536
#define GSMEM_BYTES (2 * STG)

__global__ __launch_bounds__(256) void gemm_bf3(
    const __nv_bfloat16* __restrict__ Ahi, const __nv_bfloat16* __restrict__ Alo,
    const __nv_bfloat16* __restrict__ Bhi, const __nv_bfloat16* __restrict__ Blo,
    float* __restrict__ C, int M, int N, int K) {
    extern __shared__ char sm[];
    const uint32_t sb = smem_u32(sm);
    const int tid = threadIdx.x;
    const int warp = tid >> 5, lane = tid & 31;
    const int row0 = blockIdx.y * 128;
    const int col0 = blockIdx.x * 128;

    const int wm0 = (warp & 1) * 64;
    const int wn0 = (warp >> 1) * 32;
    const int a_rif = lane & 15;
    const int a_kb = (lane >> 4) * 16;
    const int b_nrow = (lane & 7) + ((lane >> 4) & 1) * 8;
    const int b_kb = ((lane >> 3) & 1) * 16;

    // cp.async mapping: 1024 16B-chunks per 16KB buffer; thread does 4 per buffer.
    const int c_m = tid >> 1;          // base row for i=0 (cid = tid + i*256 -> m = cid>>3)
    (void)c_m;

    float c[4][4][4];
#pragma unroll
    for (int mf = 0; mf < 4; mf++)
#pragma unroll
        for (int nf = 0; nf < 4; nf++)
#pragma unroll
            for (int i = 0; i < 4; i++) c[mf][nf][i] = 0.0f;

    const int nchunks = K >> 6;

    // ---- stage copy helper (lambda) ----
    auto copy_stage = [&](int stage, int kc) {
        const uint32_t sbase = sb + stage * STG;
        const int kb = kc << 6;
#pragma unroll
        for (int i = 0; i < 4; i++) {
            const int cid = tid + i * 256;      // 0..1023
            const int m = cid >> 3;
            const int c8 = cid & 7;
            const uint32_t off = SWZ((uint32_t)(m * 128 + c8 * 16));
            const size_t asrc = (size_t)(row0 + m) * K + kb + c8 * 8;
            const size_t bsrc = (size_t)(col0 + m) * K + kb + c8 * 8;
            cpa16(sbase + off, Ahi + asrc);
            cpa16(sbase + 16384 + off, Alo + asrc);
            cpa16(sbase + 32768 + off, Bhi + bsrc);
            cpa16(sbase + 49152 + off, Blo + bsrc);
        }
    };

    copy_stage(0, 0);
    CP_COMMIT();

    for (int kc = 0; kc < nchunks; kc++) {
        const int stage = kc & 1;
        if (kc + 1 < nchunks) {
            copy_stage(stage ^ 1, kc + 1);
            CP_COMMIT();
            CP_WAIT(1);
        } else {
            CP_WAIT(0);
        }
        __syncthreads();

        const uint32_t sbase = sb + stage * STG;
#pragma unroll
        for (int ks = 0; ks < 4; ks++) {
            uint32_t ah[4][4], al[4][4], bh[2][4], bl[2][4];
#pragma unroll
            for (int mf = 0; mf < 4; mf++) {
                const uint32_t lo = SWZ((uint32_t)((wm0 + mf * 16 + a_rif) * 128 + ks * 32 + a_kb));
                ldsm4(ah[mf][0], ah[mf][1], ah[mf][2], ah[mf][3], sbase + lo);
                ldsm4(al[mf][0], al[mf][1], al[mf][2], al[mf][3], sbase + 16384 + lo);
            }
#pragma unroll
            for (int nf2 = 0; nf2 < 2; nf2++) {
                const uint32_t lo = SWZ((uint32_t)((wn0 + nf2 * 16 + b_nrow) * 128 + ks * 32 + b_kb));
                ldsm4(bh[nf2][0], bh[nf2][1], bh[nf2][2], bh[nf2][3], sbase + 32768 + lo);
                ldsm4(bl[nf2][0], bl[nf2][1], bl[nf2][2], bl[nf2][3], sbase + 49152 + lo);
            }
#pragma unroll
            for (int mf = 0; mf < 4; mf++)
#pragma unroll
                for (int nf = 0; nf < 4; nf++) {
                    const int g = nf >> 1, h2 = (nf & 1) * 2;
                    mma_bf16(c[mf][nf], ah[mf], bh[g][h2], bh[g][h2 + 1]);
                    mma_bf16(c[mf][nf], al[mf], bh[g][h2], bh[g][h2 + 1]);
                    mma_bf16(c[mf][nf], ah[mf], bl[g][h2], bl[g][h2 + 1]);
                }
        }
        __syncthreads();
    }

    // ---- Epilogue ----
    const int erow = (lane >> 2);
    const int ecol = (lane & 3) * 2;
#pragma unroll
    for (int mf = 0; mf < 4; mf++) {
        const int row = row0 + wm0 + mf * 16 + erow;
#pragma unroll
        for (int nf = 0; nf < 4; nf++) {
            const int col = col0 + wn0 + nf * 8 + ecol;
            *(float2*)(C + (size_t)row * N + col) = make_float2(c[mf][nf][0], c[mf][nf][1]);
            *(float2*)(C + (size_t)(row + 8) * N + col) = make_float2(c[mf][nf][2], c[mf][nf][3]);
        }
    }
}

// ---------------------------------------------------------------------------
// Fused RMSNorm + RoPE, in-place on g_qkv.
// ---------------------------------------------------------------------------
__global__ void rmsnorm_rope_kernel(const int* __restrict__ positions,
                                    const float* __restrict__ qw,
                                    const float* __restrict__ kw) {
    const int t = blockIdx.x;
    float* q = g_qkv + (size_t)t * QKV_N;
    float* k = q + H_DIM;

    __shared__ float sh[32];
    const int lane = threadIdx.x & 31, warp = threadIdx.x >> 5;

    float sq = 0.0f, sk = 0.0f;
    for (int i = threadIdx.x; i < H_DIM; i += 256) {
        float a = q[i]; sq += a * a;
        float b = k[i]; sk += b * b;
    }
#pragma unroll
    for (int o = 16; o; o >>= 1) sq += __shfl_xor_sync(~0u, sq, o);
    if (lane == 0) sh[warp] = sq;
    __syncthreads();
    if (threadIdx.x < 32) {
        float v = (threadIdx.x < 8) ? sh[threadIdx.x] : 0.0f;
#pragma unroll
        for (int o = 4; o; o >>= 1) v += __shfl_xor_sync(~0u, v, o);
        if (threadIdx.x == 0) sh[0] = v;
    }
    __syncthreads();
    const float invq = rsqrtf(sh[0] / (float)H_DIM + EPS_V);
    __syncthreads();
#pragma unroll
    for (int o = 16; o; o >>= 1) sk += __shfl_xor_sync(~0u, sk, o);
    if (lane == 0) sh[warp] = sk;
    __syncthreads();
    if (threadIdx.x < 32) {
        float v = (threadIdx.x < 8) ? sh[threadIdx.x] : 0.0f;
#pragma unroll
        for (int o = 4; o; o >>= 1) v += __shfl_xor_sync(~0u, v, o);
        if (threadIdx.x == 0) sh[0] = v;
    }
    __syncthreads();
    const float invk = rsqrtf(sh[0] / (float)H_DIM + EPS_V);
    __syncthreads();

    const float p = (float)positions[t];
    for (int idx = threadIdx.x; idx < NHEAD * (HDIM / 2); idx += 256) {
        const int h = idx >> 6;
        const int d = idx & 63;
        const int i1 = h * HDIM + d;
        const int i2 = i1 + (HDIM / 2);
        const float fr = p * __expf(-LOG_THETA * (float)d * (1.0f / 64.0f));
        float cc, ss;
        __sincosf(fr, &ss, &cc);

        float q1 = q[i1] * invq * qw[i1];
        float q2 = q[i2] * invq * qw[i2];
        q[i1] = q1 * cc - q2 * ss;
        q[i2] = q2 * cc + q1 * ss;

        float k1 = k[i1] * invk * kw[i1];
        float k2 = k[i2] * invk * kw[i2];
        k[i1] = k1 * cc - k2 * ss;
        k[i2] = k2 * cc + k1 * ss;
    }
}

// ---------------------------------------------------------------------------
// Flash attention (fp32): one block per (head, 64-q-row tile). 256 threads.
// ---------------------------------------------------------------------------
#define QT 64
#define KT 64
#define KPAD (HDIM + 4)
#define SM_QS 0
#define SM_KS (SM_QS + QT * HDIM)
#define SM_VS (SM_KS + KT * KPAD)
#define SM_PS (SM_VS + KT * HDIM)
#define SM_FLOATS (SM_PS + QT * KT)
#define SM_BYTES (SM_FLOATS * 4)

__global__ void flash_attn() {
    extern __shared__ float smf[];
    float* Qs = smf + SM_QS;
    float* Ks = smf + SM_KS;
    float* Vs = smf + SM_VS;
    float* Ps = smf + SM_PS;

    const int h = blockIdx.y;
    const int qt = gridDim.x - 1 - blockIdx.x;  // heavy tiles first
    const int q0 = qt * QT;
    const int tid = threadIdx.x;
    const int warp = tid >> 5, lane = tid & 31;

    for (int i = tid; i < QT * (HDIM / 4); i += 256) {
        int q = i >> 5;
        int d4 = (i & 31) * 4;
        float4 v = *(const float4*)(g_qkv + (size_t)(q0 + q) * QKV_N + h * HDIM + d4);
        v.x *= SCALE_V; v.y *= SCALE_V; v.z *= SCALE_V; v.w *= SCALE_V;
        *(float4*)&Qs[q * HDIM + d4] = v;
    }

    float m[8], l[8], acc[8][4];
#pragma unroll
    for (int i = 0; i < 8; i++) {
        m[i] = -1e30f; l[i] = 0.0f;
#pragma unroll
        for (int j = 0; j < 4; j++) acc[i][j] = 0.0f;
    }

    const int ntiles = qt + 1;
    for (int t = 0; t < ntiles; t++) {
        const int k0 = t * KT;
        __syncthreads();
        for (int i = tid; i < KT * (HDIM / 4); i += 256) {
            int k = i >> 5;
            int d4 = (i & 31) * 4;
            const float* base = g_qkv + (size_t)(k0 + k) * QKV_N + h * HDIM + d4;
            *(float4*)&Ks[k * KPAD + d4] = *(const float4*)(base + H_DIM);
            *(float4*)&Vs[k * HDIM + d4] = *(const float4*)(base + 2 * H_DIM);
        }
        __syncthreads();

        float s[8][2];
#pragma unroll
        for (int qi = 0; qi < 8; qi++) { s[qi][0] = 0.0f; s[qi][1] = 0.0f; }

        const float* k0p = Ks + lane * KPAD;
        const float* k1p = Ks + (lane + 32) * KPAD;
#pragma unroll 4
        for (int d = 0; d < HDIM; d += 4) {
            float4 ka = *(const float4*)(k0p + d);
            float4 kb = *(const float4*)(k1p + d);
#pragma unroll
            for (int qi = 0; qi < 8; qi++) {
                float4 qv = *(const float4*)&Qs[(warp * 8 + qi) * HDIM + d];
                s[qi][0] += qv.x * ka.x + qv.y * ka.y + qv.z * ka.z + qv.w * ka.w;
                s[qi][1] += qv.x * kb.x + qv.y * kb.y + qv.z * kb.z + qv.w * kb.w;
            }
        }

        if (t == qt) {
#pragma unroll
            for (int qi = 0; qi < 8; qi++) {
                int qloc = warp * 8 + qi;
                if (lane > qloc) s[qi][0] = -1e30f;
                if (lane + 32 > qloc) s[qi][1] = -1e30f;
            }
        }

#pragma unroll
        for (int qi = 0; qi < 8; qi++) {
            float mt = fmaxf(s[qi][0], s[qi][1]);
#pragma unroll
            for (int o = 16; o; o >>= 1) mt = fmaxf(mt, __shfl_xor_sync(~0u, mt, o));
            float mnew = fmaxf(m[qi], mt);
            float corr = __expf(m[qi] - mnew);
            float p0 = __expf(s[qi][0] - mnew);
            float p1 = __expf(s[qi][1] - mnew);
            float ps = p0 + p1;
#pragma unroll
            for (int o = 16; o; o >>= 1) ps += __shfl_xor_sync(~0u, ps, o);
            l[qi] = l[qi] * corr + ps;
            m[qi] = mnew;
#pragma unroll
            for (int j = 0; j < 4; j++) acc[qi][j] *= corr;
            Ps[(warp * 8 + qi) * KT + lane] = p0;
            Ps[(warp * 8 + qi) * KT + lane + 32] = p1;
        }
        __syncwarp();

#pragma unroll 4
        for (int kk = 0; kk < KT; kk += 2) {
            float4 v0 = *(const float4*)&Vs[kk * HDIM + lane * 4];
            float4 v1 = *(const float4*)&Vs[(kk + 1) * HDIM + lane * 4];
#pragma unroll
            for (int qi = 0; qi < 8; qi++) {
                float2 p = *(const float2*)&Ps[(warp * 8 + qi) * KT + kk];
                acc[qi][0] += p.x * v0.x + p.y * v1.x;
                acc[qi][1] += p.x * v0.y + p.y * v1.y;
                acc[qi][2] += p.x * v0.z + p.y * v1.z;
                acc[qi][3] += p.x * v0.w + p.y * v1.w;
            }
        }
    }

#pragma unroll
    for (int qi = 0; qi < 8; qi++) {
        float inv = 1.0f / l[qi];
        float4 o = make_float4(acc[qi][0] * inv, acc[qi][1] * inv,
                               acc[qi][2] * inv, acc[qi][3] * inv);
        *(float4*)(g_attn + (size_t)(q0 + warp * 8 + qi) * H_DIM + h * HDIM + lane * 4) = o;
    }
}

// ---------------------------------------------------------------------------
extern "C" void kernel_launch(void* const* d_in, const int* in_sizes, int n_in,
                              void* d_out, int out_size) {
    const int* positions = (const int*)d_in[0];
    const float* hidden = (const float*)d_in[1];
    const float* w_qkv = (const float*)d_in[2];
    const float* q_norm_w = (const float*)d_in[3];
    const float* k_norm_w = (const float*)d_in[4];
    const float* w_o = (const float*)d_in[5];
    float* out = (float*)d_out;

    void *p_qkv, *p_attn, *p_hh, *p_hl, *p_qh, *p_ql, *p_oh, *p_ol, *p_ah, *p_al;
    cudaGetSymbolAddress(&p_qkv, g_qkv);
    cudaGetSymbolAddress(&p_attn, g_attn);
    cudaGetSymbolAddress(&p_hh, g_hid_hi);
    cudaGetSymbolAddress(&p_hl, g_hid_lo);
    cudaGetSymbolAddress(&p_qh, g_wqkv_hi);
    cudaGetSymbolAddress(&p_ql, g_wqkv_lo);
    cudaGetSymbolAddress(&p_oh, g_wo_hi);
    cudaGetSymbolAddress(&p_ol, g_wo_lo);
    cudaGetSymbolAddress(&p_ah, g_at_hi);
    cudaGetSymbolAddress(&p_al, g_at_lo);

    cudaFuncSetAttribute(gemm_bf3, cudaFuncAttributeMaxDynamicSharedMemorySize, GSMEM_BYTES);
    cudaFuncSetAttribute(flash_attn, cudaFuncAttributeMaxDynamicSharedMemorySize, SM_BYTES);

    // 0) Convert operands to bf16 hi/lo
    convert_nt<<<(T_DIM * H_DIM / 4 + 255) / 256, 256>>>(
        hidden, (__nv_bfloat16*)p_hh, (__nv_bfloat16*)p_hl, T_DIM * H_DIM / 4);
    {
        dim3 g(QKV_N / 32, H_DIM / 32), b(32, 8);
        convert_t<<<g, b>>>(w_qkv, (__nv_bfloat16*)p_qh, (__nv_bfloat16*)p_ql, H_DIM, QKV_N);
    }
    {
        dim3 g(H_DIM / 32, H_DIM / 32), b(32, 8);
        convert_t<<<g, b>>>(w_o, (__nv_bfloat16*)p_oh, (__nv_bfloat16*)p_ol, H_DIM, H_DIM);
    }

    // 1) QKV projection
    {
        dim3 grid(QKV_N / 128, T_DIM / 128);
        gemm_bf3<<<grid, 256, GSMEM_BYTES>>>(
            (const __nv_bfloat16*)p_hh, (const __nv_bfloat16*)p_hl,
            (const __nv_bfloat16*)p_qh, (const __nv_bfloat16*)p_ql,
            (float*)p_qkv, T_DIM, QKV_N, H_DIM);
    }
    // 2) RMSNorm + RoPE
    rmsnorm_rope_kernel<<<T_DIM, 256>>>(positions, q_norm_w, k_norm_w);
    // 3) Causal flash attention
    {
        dim3 grid(T_DIM / QT, NHEAD);
        flash_attn<<<grid, 256, SM_BYTES>>>();
    }
    // 3b) Convert attention output
    convert_nt<<<(T_DIM * H_DIM / 4 + 255) / 256, 256>>>(
        (const float*)p_attn, (__nv_bfloat16*)p_ah, (__nv_bfloat16*)p_al, T_DIM * H_DIM / 4);
    // 4) Output projection
    {
        dim3 grid(H_DIM / 128, T_DIM / 128);
        gemm_bf3<<<grid, 256, GSMEM_BYTES>>>(
            (const __nv_bfloat16*)p_ah, (const __nv_bfloat16*)p_al,
            (const __nv_bfloat16*)p_oh, (const __nv_bfloat16*)p_ol,
            out, T_DIM, H_DIM, H_DIM);
    }
}

// round 11
// speedup vs baseline: 3.0944x; 1.6606x over previous
#include <cuda_runtime.h>
#include <cuda_bf16.h>
#include <cstdint>

#define T_DIM 2048
#define H_DIM 2048
#define NHEAD 16
#define HDIM 128
#define QKV_N (3 * H_DIM)
#define EPS_V 1e-6f
#define SCALE_V 0.08838834764831845f   // 128^-0.5
#define LOG_THETA 13.122363377404328f  // ln(500000)

// Scratch (device globals — no runtime allocation allowed)
__device__ __align__(128) float g_qkv[(size_t)T_DIM * QKV_N];   // 48 MB
// bf16 hi/lo split operands for GEMMs
__device__ __align__(128) __nv_bfloat16 g_hid_hi[(size_t)T_DIM * H_DIM];
__device__ __align__(128) __nv_bfloat16 g_hid_lo[(size_t)T_DIM * H_DIM];
__device__ __align__(128) __nv_bfloat16 g_wqkv_hi[(size_t)QKV_N * H_DIM];  // [N][K]
__device__ __align__(128) __nv_bfloat16 g_wqkv_lo[(size_t)QKV_N * H_DIM];
__device__ __align__(128) __nv_bfloat16 g_wo_hi[(size_t)H_DIM * H_DIM];    // [N][K]
__device__ __align__(128) __nv_bfloat16 g_wo_lo[(size_t)H_DIM * H_DIM];
__device__ __align__(128) __nv_bfloat16 g_at_hi[(size_t)T_DIM * H_DIM];
__device__ __align__(128) __nv_bfloat16 g_at_lo[(size_t)T_DIM * H_DIM];
// head-major bf16 hi/lo q/k/v for attention: [NHEAD][T][HDIM]
#define QKVSZ ((size_t)NHEAD * T_DIM * HDIM)
__device__ __align__(128) __nv_bfloat16 g_q_hi[QKVSZ];
__device__ __align__(128) __nv_bfloat16 g_q_lo[QKVSZ];
__device__ __align__(128) __nv_bfloat16 g_k_hi[QKVSZ];
__device__ __align__(128) __nv_bfloat16 g_k_lo[QKVSZ];
__device__ __align__(128) __nv_bfloat16 g_v_hi[QKVSZ];
__device__ __align__(128) __nv_bfloat16 g_v_lo[QKVSZ];

__device__ __forceinline__ uint32_t smem_u32(const void* p) {
    uint32_t a;
    asm("{ .reg .u64 t; cvta.to.shared.u64 t, %1; cvt.u32.u64 %0, t; }" : "=r"(a) : "l"(p));
    return a;
}
#define SWZ(o) ((o) ^ (((o) >> 3) & 0x70))

__device__ __forceinline__ void ldsm4(uint32_t& r0, uint32_t& r1, uint32_t& r2,
                                      uint32_t& r3, uint32_t addr) {
    asm volatile("ldmatrix.sync.aligned.m8n8.x4.shared.b16 {%0,%1,%2,%3}, [%4];"
                 : "=r"(r0), "=r"(r1), "=r"(r2), "=r"(r3) : "r"(addr));
}
__device__ __forceinline__ void ldsm4t(uint32_t& r0, uint32_t& r1, uint32_t& r2,
                                       uint32_t& r3, uint32_t addr) {
    asm volatile("ldmatrix.sync.aligned.m8n8.x4.trans.shared.b16 {%0,%1,%2,%3}, [%4];"
                 : "=r"(r0), "=r"(r1), "=r"(r2), "=r"(r3) : "r"(addr));
}
__device__ __forceinline__ void mma_bf16(float* c, const uint32_t* a, uint32_t b0,
                                         uint32_t b1) {
    asm volatile(
        "mma.sync.aligned.m16n8k16.row.col.f32.bf16.bf16.f32 "
        "{%0,%1,%2,%3}, {%4,%5,%6,%7}, {%8,%9}, {%0,%1,%2,%3};"
        : "+f"(c[0]), "+f"(c[1]), "+f"(c[2]), "+f"(c[3])
        : "r"(a[0]), "r"(a[1]), "r"(a[2]), "r"(a[3]), "r"(b0), "r"(b1));
}
__device__ __forceinline__ void cpa16(uint32_t dst, const void* src) {
    asm volatile("cp.async.cg.shared.global [%0], [%1], 16;" :: "r"(dst), "l"(src));
}
#define CP_COMMIT() asm volatile("cp.async.commit_group;" ::: "memory")
#define CP_WAIT(n)  asm volatile("cp.async.wait_group %0;" :: "n"(n) : "memory")

__device__ __forceinline__ uint32_t pack_bf2(float a, float b) {
    __nv_bfloat162 t = __floats2bfloat162_rn(a, b);
    return *(uint32_t*)&t;
}
__device__ __forceinline__ void st_hl(__nv_bfloat16* hi, __nv_bfloat16* lo, size_t i,
                                      float x) {
    __nv_bfloat16 h = __float2bfloat16(x);
    hi[i] = h;
    lo[i] = __float2bfloat16(x - __bfloat162float(h));
}

// ===========================================================================
// Converters: fp32 -> bf16 hi + bf16 lo (residual)
// ===========================================================================
__global__ void convert_nt(const float* __restrict__ src, __nv_bfloat16* __restrict__ hi,
                           __nv_bfloat16* __restrict__ lo, int n4) {
    int i = blockIdx.x * blockDim.x + threadIdx.x;
    if (i >= n4) return;
    float4 v = *(const float4*)(src + (size_t)i * 4);
    __nv_bfloat162 h01 = __floats2bfloat162_rn(v.x, v.y);
    __nv_bfloat162 h23 = __floats2bfloat162_rn(v.z, v.w);
    __nv_bfloat162 l01 = __floats2bfloat162_rn(v.x - __bfloat162float(h01.x),
                                               v.y - __bfloat162float(h01.y));
    __nv_bfloat162 l23 = __floats2bfloat162_rn(v.z - __bfloat162float(h23.x),
                                               v.w - __bfloat162float(h23.y));
    *(uint2*)(hi + (size_t)i * 4) = make_uint2(*(uint32_t*)&h01, *(uint32_t*)&h23);
    *(uint2*)(lo + (size_t)i * 4) = make_uint2(*(uint32_t*)&l01, *(uint32_t*)&l23);
}

// Transposing converter: src [R][C] fp32 -> dst [C][R] bf16 hi/lo
__global__ void convert_t(const float* __restrict__ src, __nv_bfloat16* __restrict__ hi,
                          __nv_bfloat16* __restrict__ lo, int R, int C) {
    __shared__ float tile[32][33];
    const int bx = blockIdx.x * 32;
    const int by = blockIdx.y * 32;
    const int x = threadIdx.x;
#pragma unroll
    for (int y = threadIdx.y; y < 32; y += 8)
        tile[y][x] = src[(size_t)(by + y) * C + bx + x];
    __syncthreads();
#pragma unroll
    for (int y = threadIdx.y; y < 32; y += 8) {
        float v = tile[x][y];
        __nv_bfloat16 h = __float2bfloat16(v);
        __nv_bfloat16 l = __float2bfloat16(v - __bfloat162float(h));
        hi[(size_t)(bx + y) * R + by + x] = h;
        lo[(size_t)(bx + y) * R + by + x] = l;
    }
}

// ===========================================================================
// bf16 3-pass GEMM: C = A @ B^T, cp.async double-buffered.
// ===========================================================================
#define STG 65536
#define GSMEM_BYTES (2 * STG)

__global__ __launch_bounds__(256) void gemm_bf3(
    const __nv_bfloat16* __restrict__ Ahi, const __nv_bfloat16* __restrict__ Alo,
    const __nv_bfloat16* __restrict__ Bhi, const __nv_bfloat16* __restrict__ Blo,
    float* __restrict__ C, int M, int N, int K) {
    extern __shared__ char sm[];
    const uint32_t sb = smem_u32(sm);
    const int tid = threadIdx.x;
    const int warp = tid >> 5, lane = tid & 31;
    const int row0 = blockIdx.y * 128;
    const int col0 = blockIdx.x * 128;

    const int wm0 = (warp & 1) * 64;
    const int wn0 = (warp >> 1) * 32;
    const int a_rif = lane & 15;
    const int a_kb = (lane >> 4) * 16;
    const int b_nrow = (lane & 7) + ((lane >> 4) & 1) * 8;
    const int b_kb = ((lane >> 3) & 1) * 16;

    float c[4][4][4];
#pragma unroll
    for (int mf = 0; mf < 4; mf++)
#pragma unroll
        for (int nf = 0; nf < 4; nf++)
#pragma unroll
            for (int i = 0; i < 4; i++) c[mf][nf][i] = 0.0f;

    const int nchunks = K >> 6;

    auto copy_stage = [&](int stage, int kc) {
        const uint32_t sbase = sb + stage * STG;
        const int kb = kc << 6;
#pragma unroll
        for (int i = 0; i < 4; i++) {
            const int cid = tid + i * 256;
            const int m = cid >> 3;
            const int c8 = cid & 7;
            const uint32_t off = SWZ((uint32_t)(m * 128 + c8 * 16));
            const size_t asrc = (size_t)(row0 + m) * K + kb + c8 * 8;
            const size_t bsrc = (size_t)(col0 + m) * K + kb + c8 * 8;
            cpa16(sbase + off, Ahi + asrc);
            cpa16(sbase + 16384 + off, Alo + asrc);
            cpa16(sbase + 32768 + off, Bhi + bsrc);
            cpa16(sbase + 49152 + off, Blo + bsrc);
        }
    };

    copy_stage(0, 0);
    CP_COMMIT();

    for (int kc = 0; kc < nchunks; kc++) {
        const int stage = kc & 1;
        if (kc + 1 < nchunks) {
            copy_stage(stage ^ 1, kc + 1);
            CP_COMMIT();
            CP_WAIT(1);
        } else {
            CP_WAIT(0);
        }
        __syncthreads();

        const uint32_t sbase = sb + stage * STG;
#pragma unroll
        for (int ks = 0; ks < 4; ks++) {
            uint32_t ah[4][4], al[4][4], bh[2][4], bl[2][4];
#pragma unroll
            for (int mf = 0; mf < 4; mf++) {
                const uint32_t lo = SWZ((uint32_t)((wm0 + mf * 16 + a_rif) * 128 + ks * 32 + a_kb));
                ldsm4(ah[mf][0], ah[mf][1], ah[mf][2], ah[mf][3], sbase + lo);
                ldsm4(al[mf][0], al[mf][1], al[mf][2], al[mf][3], sbase + 16384 + lo);
            }
#pragma unroll
            for (int nf2 = 0; nf2 < 2; nf2++) {
                const uint32_t lo = SWZ((uint32_t)((wn0 + nf2 * 16 + b_nrow) * 128 + ks * 32 + b_kb));
                ldsm4(bh[nf2][0], bh[nf2][1], bh[nf2][2], bh[nf2][3], sbase + 32768 + lo);
                ldsm4(bl[nf2][0], bl[nf2][1], bl[nf2][2], bl[nf2][3], sbase + 49152 + lo);
            }
#pragma unroll
            for (int mf = 0; mf < 4; mf++)
#pragma unroll
                for (int nf = 0; nf < 4; nf++) {
                    const int g = nf >> 1, h2 = (nf & 1) * 2;
                    mma_bf16(c[mf][nf], ah[mf], bh[g][h2], bh[g][h2 + 1]);
                    mma_bf16(c[mf][nf], al[mf], bh[g][h2], bh[g][h2 + 1]);
                    mma_bf16(c[mf][nf], ah[mf], bl[g][h2], bl[g][h2 + 1]);
                }
        }
        __syncthreads();
    }

    const int erow = (lane >> 2);
    const int ecol = (lane & 3) * 2;
#pragma unroll
    for (int mf = 0; mf < 4; mf++) {
        const int row = row0 + wm0 + mf * 16 + erow;
#pragma unroll
        for (int nf = 0; nf < 4; nf++) {
            const int col = col0 + wn0 + nf * 8 + ecol;
            *(float2*)(C + (size_t)row * N + col) = make_float2(c[mf][nf][0], c[mf][nf][1]);
            *(float2*)(C + (size_t)(row + 8) * N + col) = make_float2(c[mf][nf][2], c[mf][nf][3]);
        }
    }
}

// ---------------------------------------------------------------------------
// Fused RMSNorm + RoPE: reads g_qkv fp32, writes head-major bf16 hi/lo q/k/v.
// q is pre-scaled by SCALE_V.
// ---------------------------------------------------------------------------
__global__ void rmsnorm_rope_kernel(const int* __restrict__ positions,
                                    const float* __restrict__ qw,
                                    const float* __restrict__ kw) {
    const int t = blockIdx.x;
    const float* q = g_qkv + (size_t)t * QKV_N;
    const float* k = q + H_DIM;
    const float* v = q + 2 * H_DIM;

    __shared__ float sh[32];
    const int lane = threadIdx.x & 31, warp = threadIdx.x >> 5;

    float sq = 0.0f, sk = 0.0f;
    for (int i = threadIdx.x; i < H_DIM; i += 256) {
        float a = q[i]; sq += a * a;
        float b = k[i]; sk += b * b;
    }
#pragma unroll
    for (int o = 16; o; o >>= 1) sq += __shfl_xor_sync(~0u, sq, o);
    if (lane == 0) sh[warp] = sq;
    __syncthreads();
    if (threadIdx.x < 32) {
        float x = (threadIdx.x < 8) ? sh[threadIdx.x] : 0.0f;
#pragma unroll
        for (int o = 4; o; o >>= 1) x += __shfl_xor_sync(~0u, x, o);
        if (threadIdx.x == 0) sh[0] = x;
    }
    __syncthreads();
    const float invq = rsqrtf(sh[0] / (float)H_DIM + EPS_V);
    __syncthreads();
#pragma unroll
    for (int o = 16; o; o >>= 1) sk += __shfl_xor_sync(~0u, sk, o);
    if (lane == 0) sh[warp] = sk;
    __syncthreads();
    if (threadIdx.x < 32) {
        float x = (threadIdx.x < 8) ? sh[threadIdx.x] : 0.0f;
#pragma unroll
        for (int o = 4; o; o >>= 1) x += __shfl_xor_sync(~0u, x, o);
        if (threadIdx.x == 0) sh[0] = x;
    }
    __syncthreads();
    const float invk = rsqrtf(sh[0] / (float)H_DIM + EPS_V);
    __syncthreads();

    const float p = (float)positions[t];
    for (int idx = threadIdx.x; idx < NHEAD * (HDIM / 2); idx += 256) {
        const int h = idx >> 6;
        const int d = idx & 63;
        const int i1 = h * HDIM + d;
        const int i2 = i1 + 64;
        const float fr = p * __expf(-LOG_THETA * (float)d * (1.0f / 64.0f));
        float cc, ss;
        __sincosf(fr, &ss, &cc);

        float q1 = q[i1] * invq * qw[i1];
        float q2 = q[i2] * invq * qw[i2];
        float qa = (q1 * cc - q2 * ss) * SCALE_V;
        float qb = (q2 * cc + q1 * ss) * SCALE_V;
        float k1 = k[i1] * invk * kw[i1];
        float k2 = k[i2] * invk * kw[i2];
        float ka = k1 * cc - k2 * ss;
        float kb = k2 * cc + k1 * ss;

        const size_t base = ((size_t)h * T_DIM + t) * HDIM;
        st_hl(g_q_hi, g_q_lo, base + d, qa);
        st_hl(g_q_hi, g_q_lo, base + 64 + d, qb);
        st_hl(g_k_hi, g_k_lo, base + d, ka);
        st_hl(g_k_hi, g_k_lo, base + 64 + d, kb);
    }
    for (int i = threadIdx.x; i < H_DIM; i += 256) {
        const int h = i >> 7, d = i & 127;
        st_hl(g_v_hi, g_v_lo, ((size_t)h * T_DIM + t) * HDIM + d, v[i]);
    }
}

// ===========================================================================
// Tensor-core flash attention. Block = (head, 128-q tile), 256 threads.
// Warp w owns q rows [w*16, w*16+16). Key tiles of 64, double-buffered.
// 3-pass hi/lo split for both QK and PV. Writes g_at hi/lo directly.
// smem stage (64 KB): KHI 0 | KLO 16K | VHI 32K | VLO 48K. 2 stages.
// Row layout: 64 rows x 256B, chunk swizzle c^(row&7).
// ===========================================================================
#define AQT 128
#define AKT 64
#define ASTG 65536
#define ASMEM_BYTES (2 * ASTG)

__global__ __launch_bounds__(256) void attn_mma() {
    extern __shared__ char sm[];
    const uint32_t sb = smem_u32(sm);
    const int h = blockIdx.y;
    const int qt = gridDim.x - 1 - blockIdx.x;  // heavy tiles first
    const int q0 = qt * AQT;
    const int tid = threadIdx.x;
    const int warp = tid >> 5, lane = tid & 31;
    const size_t hbase = (size_t)h * T_DIM;

    auto copy_kv = [&](int stage, int t) {
        const uint32_t sbase = sb + stage * ASTG;
        const int k0 = t * AKT;
#pragma unroll
        for (int i = 0; i < 4; i++) {
            const int cid = tid + i * 256;          // 0..1023
            const int row = cid >> 4, c = cid & 15;
            const uint32_t off = (uint32_t)(row * 256 + ((c ^ (row & 7)) << 4));
            const size_t src = (hbase + k0 + row) * HDIM + c * 8;
            cpa16(sbase + off, g_k_hi + src);
            cpa16(sbase + 16384 + off, g_k_lo + src);
            cpa16(sbase + 32768 + off, g_v_hi + src);
            cpa16(sbase + 49152 + off, g_v_lo + src);
        }
    };

    // ---- Q into stage-1 area (consumed to regs before tile 1 overwrites) ----
#pragma unroll
    for (int i = 0; i < 8; i++) {
        const int cid = tid + i * 256;              // 0..2047
        const int row = cid >> 4, c = cid & 15;
        const uint32_t off = (uint32_t)(row * 256 + ((c ^ (row & 7)) << 4));
        const size_t src = (hbase + q0 + row) * HDIM + c * 8;
        cpa16(sb + ASTG + off, g_q_hi + src);
        cpa16(sb + ASTG + 32768 + off, g_q_lo + src);
    }
    CP_COMMIT();
    copy_kv(0, 0);
    CP_COMMIT();
    CP_WAIT(1);
    __syncthreads();

    // ---- Q frags ----
    uint32_t qhi[8][4], qlo[8][4];
    {
        const int arow = warp * 16 + (lane & 15);
        const int cb = lane >> 4;
#pragma unroll
        for (int ks = 0; ks < 8; ks++) {
            const int c = ks * 2 + cb;
            const uint32_t off = (uint32_t)(arow * 256 + ((c ^ (arow & 7)) << 4));
            ldsm4(qhi[ks][0], qhi[ks][1], qhi[ks][2], qhi[ks][3], sb + ASTG + off);
            ldsm4(qlo[ks][0], qlo[ks][1], qlo[ks][2], qlo[ks][3], sb + ASTG + 32768 + off);
        }
    }

    float O[16][4];
#pragma unroll
    for (int nf = 0; nf < 16; nf++)
#pragma unroll
        for (int i = 0; i < 4; i++) O[nf][i] = 0.0f;
    float m0 = -1e30f, m1 = -1e30f, l0 = 0.0f, l1 = 0.0f;

    const int r0q = q0 + warp * 16 + (lane >> 2);
    const int r1q = r0q + 8;
    const int kcol = (lane & 3) * 2;

    const int ntiles = 2 * qt + 2;
    for (int t = 0; t < ntiles; t++) {
        __syncthreads();
        if (t + 1 < ntiles) {
            copy_kv((t + 1) & 1, t + 1);
            CP_COMMIT();
            CP_WAIT(1);
        } else {
            CP_WAIT(0);
        }
        __syncthreads();
        const uint32_t st = sb + (t & 1) * ASTG;

        // ---- S = Q K^T (3-pass) ----
        float S[8][4];
#pragma unroll
        for (int nf = 0; nf < 8; nf++)
#pragma unroll
            for (int i = 0; i < 4; i++) S[nf][i] = 0.0f;

        {
            const int nrow_b = (lane & 7) + ((lane >> 4) & 1) * 8;
            const int cb = (lane >> 3) & 1;
#pragma unroll
            for (int ks = 0; ks < 8; ks++) {
#pragma unroll
                for (int g = 0; g < 4; g++) {
                    const int nrow = g * 16 + nrow_b;
                    const int c = ks * 2 + cb;
                    const uint32_t off = (uint32_t)(nrow * 256 + ((c ^ (nrow & 7)) << 4));
                    uint32_t kb0, kb1, kb2, kb3;
                    ldsm4(kb0, kb1, kb2, kb3, st + off);
                    mma_bf16(S[2 * g], qhi[ks], kb0, kb1);
                    mma_bf16(S[2 * g + 1], qhi[ks], kb2, kb3);
                    mma_bf16(S[2 * g], qlo[ks], kb0, kb1);
                    mma_bf16(S[2 * g + 1], qlo[ks], kb2, kb3);
                    ldsm4(kb0, kb1, kb2, kb3, st + 16384 + off);
                    mma_bf16(S[2 * g], qhi[ks], kb0, kb1);
                    mma_bf16(S[2 * g + 1], qhi[ks], kb2, kb3);
                }
            }
        }

        // ---- causal mask (last two tiles only) ----
        const int k0 = t * AKT;
        if (t >= 2 * qt) {
#pragma unroll
            for (int nf = 0; nf < 8; nf++) {
                const int kg = k0 + nf * 8 + kcol;
                if (kg > r0q) S[nf][0] = -1e30f;
                if (kg + 1 > r0q) S[nf][1] = -1e30f;
                if (kg > r1q) S[nf][2] = -1e30f;
                if (kg + 1 > r1q) S[nf][3] = -1e30f;
            }
        }

        // ---- online softmax ----
        float mx0 = -1e30f, mx1 = -1e30f;
#pragma unroll
        for (int nf = 0; nf < 8; nf++) {
            mx0 = fmaxf(mx0, fmaxf(S[nf][0], S[nf][1]));
            mx1 = fmaxf(mx1, fmaxf(S[nf][2], S[nf][3]));
        }
        mx0 = fmaxf(mx0, __shfl_xor_sync(~0u, mx0, 1));
        mx0 = fmaxf(mx0, __shfl_xor_sync(~0u, mx0, 2));
        mx1 = fmaxf(mx1, __shfl_xor_sync(~0u, mx1, 1));
        mx1 = fmaxf(mx1, __shfl_xor_sync(~0u, mx1, 2));
        const float mn0 = fmaxf(m0, mx0), mn1 = fmaxf(m1, mx1);
        const float cr0 = __expf(m0 - mn0), cr1 = __expf(m1 - mn1);
        float s0 = 0.0f, s1 = 0.0f;
#pragma unroll
        for (int nf = 0; nf < 8; nf++) {
            S[nf][0] = __expf(S[nf][0] - mn0);
            S[nf][1] = __expf(S[nf][1] - mn0);
            S[nf][2] = __expf(S[nf][2] - mn1);
            S[nf][3] = __expf(S[nf][3] - mn1);
            s0 += S[nf][0] + S[nf][1];
            s1 += S[nf][2] + S[nf][3];
        }
        s0 += __shfl_xor_sync(~0u, s0, 1);
        s0 += __shfl_xor_sync(~0u, s0, 2);
        s1 += __shfl_xor_sync(~0u, s1, 1);
        s1 += __shfl_xor_sync(~0u, s1, 2);
        l0 = l0 * cr0 + s0;
        l1 = l1 * cr1 + s1;
        m0 = mn0; m1 = mn1;
#pragma unroll
        for (int nf = 0; nf < 16; nf++) {
            O[nf][0] *= cr0; O[nf][1] *= cr0;
            O[nf][2] *= cr1; O[nf][3] *= cr1;
        }

        // ---- PV (3-pass), P frags from S registers ----
        {
            const int vrow_b = lane & 15;
            const int cb = lane >> 4;
#pragma unroll
            for (int kp = 0; kp < 4; kp++) {
                uint32_t ahi[4], alo[4];
                {
                    const float x0 = S[2 * kp][0], x1 = S[2 * kp][1];
                    const float x2 = S[2 * kp][2], x3 = S[2 * kp][3];
                    const float y0 = S[2 * kp + 1][0], y1 = S[2 * kp + 1][1];
                    const float y2 = S[2 * kp + 1][2], y3 = S[2 * kp + 1][3];
                    ahi[0] = pack_bf2(x0, x1);
                    ahi[1] = pack_bf2(x2, x3);
                    ahi[2] = pack_bf2(y0, y1);
                    ahi[3] = pack_bf2(y2, y3);
                    __nv_bfloat162* hp;
                    hp = (__nv_bfloat162*)&ahi[0];
                    alo[0] = pack_bf2(x0 - __bfloat162float(hp->x), x1 - __bfloat162float(hp->y));
                    hp = (__nv_bfloat162*)&ahi[1];
                    alo[1] = pack_bf2(x2 - __bfloat162float(hp->x), x3 - __bfloat162float(hp->y));
                    hp = (__nv_bfloat162*)&ahi[2];
                    alo[2] = pack_bf2(y0 - __bfloat162float(hp->x), y1 - __bfloat162float(hp->y));
                    hp = (__nv_bfloat162*)&ahi[3];
                    alo[3] = pack_bf2(y2 - __bfloat162float(hp->x), y3 - __bfloat162float(hp->y));
                }
                const int vrow = kp * 16 + vrow_b;
#pragma unroll
                for (int jj = 0; jj < 8; jj++) {
                    const int c = jj * 2 + cb;
                    const uint32_t off = (uint32_t)(vrow * 256 + ((c ^ (vrow & 7)) << 4));
                    uint32_t vb0, vb1, vb2, vb3;
                    ldsm4t(vb0, vb1, vb2, vb3, st + 32768 + off);
                    mma_bf16(O[2 * jj], ahi, vb0, vb1);
                    mma_bf16(O[2 * jj + 1], ahi, vb2, vb3);
                    mma_bf16(O[2 * jj], alo, vb0, vb1);
                    mma_bf16(O[2 * jj + 1], alo, vb2, vb3);
                    ldsm4t(vb0, vb1, vb2, vb3, st + 49152 + off);
                    mma_bf16(O[2 * jj], ahi, vb0, vb1);
                    mma_bf16(O[2 * jj + 1], ahi, vb2, vb3);
                }
            }
        }
    }

    // ---- epilogue: normalize, split to bf16 hi/lo, store ----
    const float inv0 = 1.0f / l0, inv1 = 1.0f / l1;
    const size_t row0o = (size_t)(q0 + warp * 16 + (lane >> 2)) * H_DIM;
    const size_t row1o = row0o + 8 * H_DIM;
#pragma unroll
    for (int nf = 0; nf < 16; nf++) {
        const int d = h * HDIM + nf * 8 + kcol;
        float v0 = O[nf][0] * inv0, v1 = O[nf][1] * inv0;
        float v2 = O[nf][2] * inv1, v3 = O[nf][3] * inv1;
        uint32_t h0 = pack_bf2(v0, v1);
        __nv_bfloat162* hp = (__nv_bfloat162*)&h0;
        uint32_t l0p = pack_bf2(v0 - __bfloat162float(hp->x), v1 - __bfloat162float(hp->y));
        uint32_t h1 = pack_bf2(v2, v3);
        hp = (__nv_bfloat162*)&h1;
        uint32_t l1p = pack_bf2(v2 - __bfloat162float(hp->x), v3 - __bfloat162float(hp->y));
        *(uint32_t*)(g_at_hi + row0o + d) = h0;
        *(uint32_t*)(g_at_lo + row0o + d) = l0p;
        *(uint32_t*)(g_at_hi + row1o + d) = h1;
        *(uint32_t*)(g_at_lo + row1o + d) = l1p;
    }
}

// ---------------------------------------------------------------------------
extern "C" void kernel_launch(void* const* d_in, const int* in_sizes, int n_in,
                              void* d_out, int out_size) {
    const int* positions = (const int*)d_in[0];
    const float* hidden = (const float*)d_in[1];
    const float* w_qkv = (const float*)d_in[2];
    const float* q_norm_w = (const float*)d_in[3];
    const float* k_norm_w = (const float*)d_in[4];
    const float* w_o = (const float*)d_in[5];
    float* out = (float*)d_out;

    void *p_qkv, *p_hh, *p_hl, *p_qh, *p_ql, *p_oh, *p_ol, *p_ah, *p_al;
    cudaGetSymbolAddress(&p_qkv, g_qkv);
    cudaGetSymbolAddress(&p_hh, g_hid_hi);
    cudaGetSymbolAddress(&p_hl, g_hid_lo);
    cudaGetSymbolAddress(&p_qh, g_wqkv_hi);
    cudaGetSymbolAddress(&p_ql, g_wqkv_lo);
    cudaGetSymbolAddress(&p_oh, g_wo_hi);
    cudaGetSymbolAddress(&p_ol, g_wo_lo);
    cudaGetSymbolAddress(&p_ah, g_at_hi);
    cudaGetSymbolAddress(&p_al, g_at_lo);

    cudaFuncSetAttribute(gemm_bf3, cudaFuncAttributeMaxDynamicSharedMemorySize, GSMEM_BYTES);
    cudaFuncSetAttribute(attn_mma, cudaFuncAttributeMaxDynamicSharedMemorySize, ASMEM_BYTES);

    // 0) Convert GEMM operands to bf16 hi/lo
    convert_nt<<<(T_DIM * H_DIM / 4 + 255) / 256, 256>>>(
        hidden, (__nv_bfloat16*)p_hh, (__nv_bfloat16*)p_hl, T_DIM * H_DIM / 4);
    {
        dim3 g(QKV_N / 32, H_DIM / 32), b(32, 8);
        convert_t<<<g, b>>>(w_qkv, (__nv_bfloat16*)p_qh, (__nv_bfloat16*)p_ql, H_DIM, QKV_N);
    }
    {
        dim3 g(H_DIM / 32, H_DIM / 32), b(32, 8);
        convert_t<<<g, b>>>(w_o, (__nv_bfloat16*)p_oh, (__nv_bfloat16*)p_ol, H_DIM, H_DIM);
    }

    // 1) QKV projection
    {
        dim3 grid(QKV_N / 128, T_DIM / 128);
        gemm_bf3<<<grid, 256, GSMEM_BYTES>>>(
            (const __nv_bfloat16*)p_hh, (const __nv_bfloat16*)p_hl,
            (const __nv_bfloat16*)p_qh, (const __nv_bfloat16*)p_ql,
            (float*)p_qkv, T_DIM, QKV_N, H_DIM);
    }
    // 2) RMSNorm + RoPE -> bf16 hi/lo q/k/v (head-major)
    rmsnorm_rope_kernel<<<T_DIM, 256>>>(positions, q_norm_w, k_norm_w);
    // 3) Tensor-core causal flash attention -> g_at hi/lo
    {
        dim3 grid(T_DIM / AQT, NHEAD);
        attn_mma<<<grid, 256, ASMEM_BYTES>>>();
    }
    // 4) Output projection
    {
        dim3 grid(H_DIM / 128, T_DIM / 128);
        gemm_bf3<<<grid, 256, GSMEM_BYTES>>>(
            (const __nv_bfloat16*)p_ah, (const __nv_bfloat16*)p_al,
            (const __nv_bfloat16*)p_oh, (const __nv_bfloat16*)p_ol,
            out, T_DIM, H_DIM, H_DIM);
    }
}

// round 12
// speedup vs baseline: 3.1837x; 1.0289x over previous
#include <cuda_runtime.h>
#include <cuda_bf16.h>
#include <cstdint>

#define T_DIM 2048
#define H_DIM 2048
#define NHEAD 16
#define HDIM 128
#define QKV_N (3 * H_DIM)
#define EPS_V 1e-6f
#define SCALE_V 0.08838834764831845f   // 128^-0.5
#define LOG_THETA 13.122363377404328f  // ln(500000)

// Scratch (device globals — no runtime allocation allowed)
__device__ __align__(128) float g_qkv[(size_t)T_DIM * QKV_N];   // 48 MB
// bf16 hi/lo split operands for GEMMs
__device__ __align__(128) __nv_bfloat16 g_hid_hi[(size_t)T_DIM * H_DIM];
__device__ __align__(128) __nv_bfloat16 g_hid_lo[(size_t)T_DIM * H_DIM];
__device__ __align__(128) __nv_bfloat16 g_wqkv_hi[(size_t)QKV_N * H_DIM];  // [N][K]
__device__ __align__(128) __nv_bfloat16 g_wqkv_lo[(size_t)QKV_N * H_DIM];
__device__ __align__(128) __nv_bfloat16 g_wo_hi[(size_t)H_DIM * H_DIM];    // [N][K]
__device__ __align__(128) __nv_bfloat16 g_wo_lo[(size_t)H_DIM * H_DIM];
__device__ __align__(128) __nv_bfloat16 g_at_hi[(size_t)T_DIM * H_DIM];
__device__ __align__(128) __nv_bfloat16 g_at_lo[(size_t)T_DIM * H_DIM];
// head-major bf16 hi/lo q/k/v for attention: [NHEAD][T][HDIM]
#define QKVSZ ((size_t)NHEAD * T_DIM * HDIM)
__device__ __align__(128) __nv_bfloat16 g_q_hi[QKVSZ];
__device__ __align__(128) __nv_bfloat16 g_q_lo[QKVSZ];
__device__ __align__(128) __nv_bfloat16 g_k_hi[QKVSZ];
__device__ __align__(128) __nv_bfloat16 g_k_lo[QKVSZ];
__device__ __align__(128) __nv_bfloat16 g_v_hi[QKVSZ];
__device__ __align__(128) __nv_bfloat16 g_v_lo[QKVSZ];

__device__ __forceinline__ uint32_t smem_u32(const void* p) {
    uint32_t a;
    asm("{ .reg .u64 t; cvta.to.shared.u64 t, %1; cvt.u32.u64 %0, t; }" : "=r"(a) : "l"(p));
    return a;
}
#define SWZ(o) ((o) ^ (((o) >> 3) & 0x70))

__device__ __forceinline__ void ldsm4(uint32_t& r0, uint32_t& r1, uint32_t& r2,
                                      uint32_t& r3, uint32_t addr) {
    asm volatile("ldmatrix.sync.aligned.m8n8.x4.shared.b16 {%0,%1,%2,%3}, [%4];"
                 : "=r"(r0), "=r"(r1), "=r"(r2), "=r"(r3) : "r"(addr));
}
__device__ __forceinline__ void ldsm4t(uint32_t& r0, uint32_t& r1, uint32_t& r2,
                                       uint32_t& r3, uint32_t addr) {
    asm volatile("ldmatrix.sync.aligned.m8n8.x4.trans.shared.b16 {%0,%1,%2,%3}, [%4];"
                 : "=r"(r0), "=r"(r1), "=r"(r2), "=r"(r3) : "r"(addr));
}
__device__ __forceinline__ void mma_bf16(float* c, const uint32_t* a, uint32_t b0,
                                         uint32_t b1) {
    asm volatile(
        "mma.sync.aligned.m16n8k16.row.col.f32.bf16.bf16.f32 "
        "{%0,%1,%2,%3}, {%4,%5,%6,%7}, {%8,%9}, {%0,%1,%2,%3};"
        : "+f"(c[0]), "+f"(c[1]), "+f"(c[2]), "+f"(c[3])
        : "r"(a[0]), "r"(a[1]), "r"(a[2]), "r"(a[3]), "r"(b0), "r"(b1));
}
__device__ __forceinline__ void cpa16(uint32_t dst, const void* src) {
    asm volatile("cp.async.cg.shared.global [%0], [%1], 16;" :: "r"(dst), "l"(src));
}
#define CP_COMMIT() asm volatile("cp.async.commit_group;" ::: "memory")
#define CP_WAIT(n)  asm volatile("cp.async.wait_group %0;" :: "n"(n) : "memory")

__device__ __forceinline__ uint32_t pack_bf2(float a, float b) {
    __nv_bfloat162 t = __floats2bfloat162_rn(a, b);
    return *(uint32_t*)&t;
}
__device__ __forceinline__ uint32_t res_bf2(uint32_t hpk, float a, float b) {
    __nv_bfloat162 hp = *(__nv_bfloat162*)&hpk;
    return pack_bf2(a - __bfloat162float(hp.x), b - __bfloat162float(hp.y));
}

// ===========================================================================
// Converters: fp32 -> bf16 hi + bf16 lo (residual)
// ===========================================================================
__global__ void convert_nt(const float* __restrict__ src, __nv_bfloat16* __restrict__ hi,
                           __nv_bfloat16* __restrict__ lo, int n4) {
    int i = blockIdx.x * blockDim.x + threadIdx.x;
    if (i >= n4) return;
    float4 v = *(const float4*)(src + (size_t)i * 4);
    uint32_t h01 = pack_bf2(v.x, v.y);
    uint32_t h23 = pack_bf2(v.z, v.w);
    uint32_t l01 = res_bf2(h01, v.x, v.y);
    uint32_t l23 = res_bf2(h23, v.z, v.w);
    *(uint2*)(hi + (size_t)i * 4) = make_uint2(h01, h23);
    *(uint2*)(lo + (size_t)i * 4) = make_uint2(l01, l23);
}

// Transposing converter: src [R][C] fp32 -> dst [C][R] bf16 hi/lo
__global__ void convert_t(const float* __restrict__ src, __nv_bfloat16* __restrict__ hi,
                          __nv_bfloat16* __restrict__ lo, int R, int C) {
    __shared__ float tile[32][33];
    const int bx = blockIdx.x * 32;
    const int by = blockIdx.y * 32;
    const int x = threadIdx.x;
#pragma unroll
    for (int y = threadIdx.y; y < 32; y += 8)
        tile[y][x] = src[(size_t)(by + y) * C + bx + x];
    __syncthreads();
#pragma unroll
    for (int y = threadIdx.y; y < 32; y += 8) {
        float v = tile[x][y];
        __nv_bfloat16 h = __float2bfloat16(v);
        __nv_bfloat16 l = __float2bfloat16(v - __bfloat162float(h));
        hi[(size_t)(bx + y) * R + by + x] = h;
        lo[(size_t)(bx + y) * R + by + x] = l;
    }
}

// ===========================================================================
// bf16 3-pass GEMM: C = A @ B^T, cp.async 3-stage pipeline.
// Stage (64 KB): AHI 0 | ALO 16K | BHI 32K | BLO 48K. 3 stages = 192 KB.
// ===========================================================================
#define STG 65536
#define GSMEM_BYTES (3 * STG)

__global__ __launch_bounds__(256) void gemm_bf3(
    const __nv_bfloat16* __restrict__ Ahi, const __nv_bfloat16* __restrict__ Alo,
    const __nv_bfloat16* __restrict__ Bhi, const __nv_bfloat16* __restrict__ Blo,
    float* __restrict__ C, int M, int N, int K) {
    extern __shared__ char sm[];
    const uint32_t sb = smem_u32(sm);
    const int tid = threadIdx.x;
    const int warp = tid >> 5, lane = tid & 31;
    const int row0 = blockIdx.y * 128;
    const int col0 = blockIdx.x * 128;

    const int wm0 = (warp & 1) * 64;
    const int wn0 = (warp >> 1) * 32;
    const int a_rif = lane & 15;
    const int a_kb = (lane >> 4) * 16;
    const int b_nrow = (lane & 7) + ((lane >> 4) & 1) * 8;
    const int b_kb = ((lane >> 3) & 1) * 16;

    float c[4][4][4];
#pragma unroll
    for (int mf = 0; mf < 4; mf++)
#pragma unroll
        for (int nf = 0; nf < 4; nf++)
#pragma unroll
            for (int i = 0; i < 4; i++) c[mf][nf][i] = 0.0f;

    const int nchunks = K >> 6;

    auto copy_stage = [&](int stage, int kc) {
        const uint32_t sbase = sb + stage * STG;
        const int kb = kc << 6;
#pragma unroll
        for (int i = 0; i < 4; i++) {
            const int cid = tid + i * 256;
            const int m = cid >> 3;
            const int c8 = cid & 7;
            const uint32_t off = SWZ((uint32_t)(m * 128 + c8 * 16));
            const size_t asrc = (size_t)(row0 + m) * K + kb + c8 * 8;
            const size_t bsrc = (size_t)(col0 + m) * K + kb + c8 * 8;
            cpa16(sbase + off, Ahi + asrc);
            cpa16(sbase + 16384 + off, Alo + asrc);
            cpa16(sbase + 32768 + off, Bhi + bsrc);
            cpa16(sbase + 49152 + off, Blo + bsrc);
        }
    };

    copy_stage(0, 0);
    CP_COMMIT();
    copy_stage(1, 1);
    CP_COMMIT();

    int stage = 0;
    for (int kc = 0; kc < nchunks; kc++) {
        if (kc + 2 < nchunks) {
            copy_stage((stage + 2) % 3, kc + 2);
            CP_COMMIT();
            CP_WAIT(2);
        } else if (kc + 1 < nchunks) {
            CP_WAIT(1);
        } else {
            CP_WAIT(0);
        }
        __syncthreads();

        const uint32_t sbase = sb + stage * STG;
#pragma unroll
        for (int ks = 0; ks < 4; ks++) {
            uint32_t ah[4][4], al[4][4], bh[2][4], bl[2][4];
#pragma unroll
            for (int mf = 0; mf < 4; mf++) {
                const uint32_t lo = SWZ((uint32_t)((wm0 + mf * 16 + a_rif) * 128 + ks * 32 + a_kb));
                ldsm4(ah[mf][0], ah[mf][1], ah[mf][2], ah[mf][3], sbase + lo);
                ldsm4(al[mf][0], al[mf][1], al[mf][2], al[mf][3], sbase + 16384 + lo);
            }
#pragma unroll
            for (int nf2 = 0; nf2 < 2; nf2++) {
                const uint32_t lo = SWZ((uint32_t)((wn0 + nf2 * 16 + b_nrow) * 128 + ks * 32 + b_kb));
                ldsm4(bh[nf2][0], bh[nf2][1], bh[nf2][2], bh[nf2][3], sbase + 32768 + lo);
                ldsm4(bl[nf2][0], bl[nf2][1], bl[nf2][2], bl[nf2][3], sbase + 49152 + lo);
            }
#pragma unroll
            for (int mf = 0; mf < 4; mf++)
#pragma unroll
                for (int nf = 0; nf < 4; nf++) {
                    const int g = nf >> 1, h2 = (nf & 1) * 2;
                    mma_bf16(c[mf][nf], ah[mf], bh[g][h2], bh[g][h2 + 1]);
                    mma_bf16(c[mf][nf], al[mf], bh[g][h2], bh[g][h2 + 1]);
                    mma_bf16(c[mf][nf], ah[mf], bl[g][h2], bl[g][h2 + 1]);
                }
        }
        __syncthreads();
        stage = (stage + 1) % 3;
    }

    const int erow = (lane >> 2);
    const int ecol = (lane & 3) * 2;
#pragma unroll
    for (int mf = 0; mf < 4; mf++) {
        const int row = row0 + wm0 + mf * 16 + erow;
#pragma unroll
        for (int nf = 0; nf < 4; nf++) {
            const int col = col0 + wn0 + nf * 8 + ecol;
            *(float2*)(C + (size_t)row * N + col) = make_float2(c[mf][nf][0], c[mf][nf][1]);
            *(float2*)(C + (size_t)(row + 8) * N + col) = make_float2(c[mf][nf][2], c[mf][nf][3]);
        }
    }
}

// ---------------------------------------------------------------------------
// Fused RMSNorm + RoPE (vectorized): reads g_qkv fp32, writes head-major
// bf16 hi/lo q/k/v. q pre-scaled by SCALE_V.
// ---------------------------------------------------------------------------
__global__ void rmsnorm_rope_kernel(const int* __restrict__ positions,
                                    const float* __restrict__ qw,
                                    const float* __restrict__ kw) {
    const int t = blockIdx.x;
    const float* q = g_qkv + (size_t)t * QKV_N;
    const float* k = q + H_DIM;
    const float* v = q + 2 * H_DIM;

    __shared__ float sh[32];
    const int lane = threadIdx.x & 31, warp = threadIdx.x >> 5;

    const float4* q4 = (const float4*)q;
    const float4* k4 = (const float4*)k;
    float sq = 0.0f, sk = 0.0f;
    for (int i = threadIdx.x; i < H_DIM / 4; i += 256) {
        float4 a = q4[i];
        sq += a.x * a.x + a.y * a.y + a.z * a.z + a.w * a.w;
        float4 b = k4[i];
        sk += b.x * b.x + b.y * b.y + b.z * b.z + b.w * b.w;
    }
#pragma unroll
    for (int o = 16; o; o >>= 1) sq += __shfl_xor_sync(~0u, sq, o);
    if (lane == 0) sh[warp] = sq;
    __syncthreads();
    if (threadIdx.x < 32) {
        float x = (threadIdx.x < 8) ? sh[threadIdx.x] : 0.0f;
#pragma unroll
        for (int o = 4; o; o >>= 1) x += __shfl_xor_sync(~0u, x, o);
        if (threadIdx.x == 0) sh[0] = x;
    }
    __syncthreads();
    const float invq = rsqrtf(sh[0] / (float)H_DIM + EPS_V);
    __syncthreads();
#pragma unroll
    for (int o = 16; o; o >>= 1) sk += __shfl_xor_sync(~0u, sk, o);
    if (lane == 0) sh[warp] = sk;
    __syncthreads();
    if (threadIdx.x < 32) {
        float x = (threadIdx.x < 8) ? sh[threadIdx.x] : 0.0f;
#pragma unroll
        for (int o = 4; o; o >>= 1) x += __shfl_xor_sync(~0u, x, o);
        if (threadIdx.x == 0) sh[0] = x;
    }
    __syncthreads();
    const float invk = rsqrtf(sh[0] / (float)H_DIM + EPS_V);

    const float p = (float)positions[t];
    // RoPE: thread handles 4 consecutive pairs. h = tid>>4, d = (tid&15)*4.
    {
        const int h = threadIdx.x >> 4;
        const int dg = (threadIdx.x & 15) * 4;
        const int i1 = h * HDIM + dg;
        const int i2 = i1 + 64;
        float4 q1v = *(const float4*)(q + i1);
        float4 q2v = *(const float4*)(q + i2);
        float4 k1v = *(const float4*)(k + i1);
        float4 k2v = *(const float4*)(k + i2);
        float4 w1q = *(const float4*)(qw + i1);
        float4 w2q = *(const float4*)(qw + i2);
        float4 w1k = *(const float4*)(kw + i1);
        float4 w2k = *(const float4*)(kw + i2);

        float qa[4], qb[4], ka[4], kb[4];
        const float* q1p = &q1v.x; const float* q2p = &q2v.x;
        const float* k1p = &k1v.x; const float* k2p = &k2v.x;
        const float* w1qp = &w1q.x; const float* w2qp = &w2q.x;
        const float* w1kp = &w1k.x; const float* w2kp = &w2k.x;
#pragma unroll
        for (int j = 0; j < 4; j++) {
            const float fr = p * __expf(-LOG_THETA * (float)(dg + j) * (1.0f / 64.0f));
            float cc, ss;
            __sincosf(fr, &ss, &cc);
            float x1 = q1p[j] * invq * w1qp[j];
            float x2 = q2p[j] * invq * w2qp[j];
            qa[j] = (x1 * cc - x2 * ss) * SCALE_V;
            qb[j] = (x2 * cc + x1 * ss) * SCALE_V;
            float y1 = k1p[j] * invk * w1kp[j];
            float y2 = k2p[j] * invk * w2kp[j];
            ka[j] = y1 * cc - y2 * ss;
            kb[j] = y2 * cc + y1 * ss;
        }
        const size_t base = ((size_t)h * T_DIM + t) * HDIM;
        uint32_t h0, h1;
        h0 = pack_bf2(qa[0], qa[1]); h1 = pack_bf2(qa[2], qa[3]);
        *(uint2*)(g_q_hi + base + dg) = make_uint2(h0, h1);
        *(uint2*)(g_q_lo + base + dg) = make_uint2(res_bf2(h0, qa[0], qa[1]), res_bf2(h1, qa[2], qa[3]));
        h0 = pack_bf2(qb[0], qb[1]); h1 = pack_bf2(qb[2], qb[3]);
        *(uint2*)(g_q_hi + base + 64 + dg) = make_uint2(h0, h1);
        *(uint2*)(g_q_lo + base + 64 + dg) = make_uint2(res_bf2(h0, qb[0], qb[1]), res_bf2(h1, qb[2], qb[3]));
        h0 = pack_bf2(ka[0], ka[1]); h1 = pack_bf2(ka[2], ka[3]);
        *(uint2*)(g_k_hi + base + dg) = make_uint2(h0, h1);
        *(uint2*)(g_k_lo + base + dg) = make_uint2(res_bf2(h0, ka[0], ka[1]), res_bf2(h1, ka[2], ka[3]));
        h0 = pack_bf2(kb[0], kb[1]); h1 = pack_bf2(kb[2], kb[3]);
        *(uint2*)(g_k_hi + base + 64 + dg) = make_uint2(h0, h1);
        *(uint2*)(g_k_lo + base + 64 + dg) = make_uint2(res_bf2(h0, kb[0], kb[1]), res_bf2(h1, kb[2], kb[3]));
    }
    // V: 512 float4 over 256 threads
    {
        const float4* v4 = (const float4*)v;
#pragma unroll
        for (int it = 0; it < 2; it++) {
            const int i = threadIdx.x + it * 256;
            float4 val = v4[i];
            const int h = i >> 5;
            const int d = (i & 31) * 4;
            const size_t base = ((size_t)h * T_DIM + t) * HDIM + d;
            uint32_t h0 = pack_bf2(val.x, val.y);
            uint32_t h1 = pack_bf2(val.z, val.w);
            *(uint2*)(g_v_hi + base) = make_uint2(h0, h1);
            *(uint2*)(g_v_lo + base) = make_uint2(res_bf2(h0, val.x, val.y), res_bf2(h1, val.z, val.w));
        }
    }
}

// ===========================================================================
// Tensor-core flash attention, 3-stage cp.async pipeline.
// Block = (head, 128-q tile), 256 threads. Key tiles of 64.
// Stage (64 KB): KHI 0 | KLO 16K | VHI 32K | VLO 48K. 3 stages.
// Q preloads into stage 2 (hi at 0, lo at 32K), consumed to regs pre-loop.
// ===========================================================================
#define AQT 128
#define AKT 64
#define ASTG 65536
#define ASMEM_BYTES (3 * ASTG)

__global__ __launch_bounds__(256) void attn_mma() {
    extern __shared__ char sm[];
    const uint32_t sb = smem_u32(sm);
    const int h = blockIdx.y;
    const int qt = gridDim.x - 1 - blockIdx.x;  // heavy tiles first
    const int q0 = qt * AQT;
    const int tid = threadIdx.x;
    const int warp = tid >> 5, lane = tid & 31;
    const size_t hbase = (size_t)h * T_DIM;

    auto copy_kv = [&](int stage, int t) {
        const uint32_t sbase = sb + stage * ASTG;
        const int k0 = t * AKT;
#pragma unroll
        for (int i = 0; i < 4; i++) {
            const int cid = tid + i * 256;          // 0..1023
            const int row = cid >> 4, c = cid & 15;
            const uint32_t off = (uint32_t)(row * 256 + ((c ^ (row & 7)) << 4));
            const size_t src = (hbase + k0 + row) * HDIM + c * 8;
            cpa16(sbase + off, g_k_hi + src);
            cpa16(sbase + 16384 + off, g_k_lo + src);
            cpa16(sbase + 32768 + off, g_v_hi + src);
            cpa16(sbase + 49152 + off, g_v_lo + src);
        }
    };

    // ---- Q into stage 2 ----
#pragma unroll
    for (int i = 0; i < 8; i++) {
        const int cid = tid + i * 256;              // 0..2047
        const int row = cid >> 4, c = cid & 15;
        const uint32_t off = (uint32_t)(row * 256 + ((c ^ (row & 7)) << 4));
        const size_t src = (hbase + q0 + row) * HDIM + c * 8;
        cpa16(sb + 2 * ASTG + off, g_q_hi + src);
        cpa16(sb + 2 * ASTG + 32768 + off, g_q_lo + src);
    }
    CP_COMMIT();
    copy_kv(0, 0);
    CP_COMMIT();
    copy_kv(1, 1);
    CP_COMMIT();
    CP_WAIT(2);      // Q landed
    __syncthreads();

    // ---- Q frags ----
    uint32_t qhi[8][4], qlo[8][4];
    {
        const int arow = warp * 16 + (lane & 15);
        const int cb = lane >> 4;
#pragma unroll
        for (int ks = 0; ks < 8; ks++) {
            const int c = ks * 2 + cb;
            const uint32_t off = (uint32_t)(arow * 256 + ((c ^ (arow & 7)) << 4));
            ldsm4(qhi[ks][0], qhi[ks][1], qhi[ks][2], qhi[ks][3], sb + 2 * ASTG + off);
            ldsm4(qlo[ks][0], qlo[ks][1], qlo[ks][2], qlo[ks][3], sb + 2 * ASTG + 32768 + off);
        }
    }
    __syncthreads();  // all warps done reading Q before stage 2 is recycled

    float O[16][4];
#pragma unroll
    for (int nf = 0; nf < 16; nf++)
#pragma unroll
        for (int i = 0; i < 4; i++) O[nf][i] = 0.0f;
    float m0 = -1e30f, m1 = -1e30f, l0 = 0.0f, l1 = 0.0f;

    const int r0q = q0 + warp * 16 + (lane >> 2);
    const int r1q = r0q + 8;
    const int kcol = (lane & 3) * 2;

    const int ntiles = 2 * qt + 2;
    int stage = 0;
    for (int t = 0; t < ntiles; t++) {
        if (t + 2 < ntiles) {
            copy_kv((stage + 2) % 3, t + 2);
            CP_COMMIT();
            CP_WAIT(2);
        } else if (t + 1 < ntiles) {
            CP_WAIT(1);
        } else {
            CP_WAIT(0);
        }
        __syncthreads();
        const uint32_t st = sb + stage * ASTG;

        // ---- S = Q K^T (3-pass) ----
        float S[8][4];
#pragma unroll
        for (int nf = 0; nf < 8; nf++)
#pragma unroll
            for (int i = 0; i < 4; i++) S[nf][i] = 0.0f;

        {
            const int nrow_b = (lane & 7) + ((lane >> 4) & 1) * 8;
            const int cb = (lane >> 3) & 1;
#pragma unroll
            for (int ks = 0; ks < 8; ks++) {
#pragma unroll
                for (int g = 0; g < 4; g++) {
                    const int nrow = g * 16 + nrow_b;
                    const int c = ks * 2 + cb;
                    const uint32_t off = (uint32_t)(nrow * 256 + ((c ^ (nrow & 7)) << 4));
                    uint32_t kb0, kb1, kb2, kb3;
                    ldsm4(kb0, kb1, kb2, kb3, st + off);
                    mma_bf16(S[2 * g], qhi[ks], kb0, kb1);
                    mma_bf16(S[2 * g + 1], qhi[ks], kb2, kb3);
                    mma_bf16(S[2 * g], qlo[ks], kb0, kb1);
                    mma_bf16(S[2 * g + 1], qlo[ks], kb2, kb3);
                    ldsm4(kb0, kb1, kb2, kb3, st + 16384 + off);
                    mma_bf16(S[2 * g], qhi[ks], kb0, kb1);
                    mma_bf16(S[2 * g + 1], qhi[ks], kb2, kb3);
                }
            }
        }

        // ---- causal mask (last two tiles only) ----
        const int k0 = t * AKT;
        if (t >= 2 * qt) {
#pragma unroll
            for (int nf = 0; nf < 8; nf++) {
                const int kg = k0 + nf * 8 + kcol;
                if (kg > r0q) S[nf][0] = -1e30f;
                if (kg + 1 > r0q) S[nf][1] = -1e30f;
                if (kg > r1q) S[nf][2] = -1e30f;
                if (kg + 1 > r1q) S[nf][3] = -1e30f;
            }
        }

        // ---- online softmax ----
        float mx0 = -1e30f, mx1 = -1e30f;
#pragma unroll
        for (int nf = 0; nf < 8; nf++) {
            mx0 = fmaxf(mx0, fmaxf(S[nf][0], S[nf][1]));
            mx1 = fmaxf(mx1, fmaxf(S[nf][2], S[nf][3]));
        }
        mx0 = fmaxf(mx0, __shfl_xor_sync(~0u, mx0, 1));
        mx0 = fmaxf(mx0, __shfl_xor_sync(~0u, mx0, 2));
        mx1 = fmaxf(mx1, __shfl_xor_sync(~0u, mx1, 1));
        mx1 = fmaxf(mx1, __shfl_xor_sync(~0u, mx1, 2));
        const float mn0 = fmaxf(m0, mx0), mn1 = fmaxf(m1, mx1);
        const float cr0 = __expf(m0 - mn0), cr1 = __expf(m1 - mn1);
        float s0 = 0.0f, s1 = 0.0f;
#pragma unroll
        for (int nf = 0; nf < 8; nf++) {
            S[nf][0] = __expf(S[nf][0] - mn0);
            S[nf][1] = __expf(S[nf][1] - mn0);
            S[nf][2] = __expf(S[nf][2] - mn1);
            S[nf][3] = __expf(S[nf][3] - mn1);
            s0 += S[nf][0] + S[nf][1];
            s1 += S[nf][2] + S[nf][3];
        }
        s0 += __shfl_xor_sync(~0u, s0, 1);
        s0 += __shfl_xor_sync(~0u, s0, 2);
        s1 += __shfl_xor_sync(~0u, s1, 1);
        s1 += __shfl_xor_sync(~0u, s1, 2);
        l0 = l0 * cr0 + s0;
        l1 = l1 * cr1 + s1;
        m0 = mn0; m1 = mn1;
#pragma unroll
        for (int nf = 0; nf < 16; nf++) {
            O[nf][0] *= cr0; O[nf][1] *= cr0;
            O[nf][2] *= cr1; O[nf][3] *= cr1;
        }

        // ---- PV (3-pass), P frags from S registers ----
        {
            const int vrow_b = lane & 15;
            const int cb = lane >> 4;
#pragma unroll
            for (int kp = 0; kp < 4; kp++) {
                uint32_t ahi[4], alo[4];
                {
                    const float x0 = S[2 * kp][0], x1 = S[2 * kp][1];
                    const float x2 = S[2 * kp][2], x3 = S[2 * kp][3];
                    const float y0 = S[2 * kp + 1][0], y1 = S[2 * kp + 1][1];
                    const float y2 = S[2 * kp + 1][2], y3 = S[2 * kp + 1][3];
                    ahi[0] = pack_bf2(x0, x1);
                    ahi[1] = pack_bf2(x2, x3);
                    ahi[2] = pack_bf2(y0, y1);
                    ahi[3] = pack_bf2(y2, y3);
                    alo[0] = res_bf2(ahi[0], x0, x1);
                    alo[1] = res_bf2(ahi[1], x2, x3);
                    alo[2] = res_bf2(ahi[2], y0, y1);
                    alo[3] = res_bf2(ahi[3], y2, y3);
                }
                const int vrow = kp * 16 + vrow_b;
#pragma unroll
                for (int jj = 0; jj < 8; jj++) {
                    const int c = jj * 2 + cb;
                    const uint32_t off = (uint32_t)(vrow * 256 + ((c ^ (vrow & 7)) << 4));
                    uint32_t vb0, vb1, vb2, vb3;
                    ldsm4t(vb0, vb1, vb2, vb3, st + 32768 + off);
                    mma_bf16(O[2 * jj], ahi, vb0, vb1);
                    mma_bf16(O[2 * jj + 1], ahi, vb2, vb3);
                    mma_bf16(O[2 * jj], alo, vb0, vb1);
                    mma_bf16(O[2 * jj + 1], alo, vb2, vb3);
                    ldsm4t(vb0, vb1, vb2, vb3, st + 49152 + off);
                    mma_bf16(O[2 * jj], ahi, vb0, vb1);
                    mma_bf16(O[2 * jj + 1], ahi, vb2, vb3);
                }
            }
        }
        __syncthreads();
        stage = (stage + 1) % 3;
    }

    // ---- epilogue: normalize, split to bf16 hi/lo, store ----
    const float inv0 = 1.0f / l0, inv1 = 1.0f / l1;
    const size_t row0o = (size_t)(q0 + warp * 16 + (lane >> 2)) * H_DIM;
    const size_t row1o = row0o + 8 * H_DIM;
#pragma unroll
    for (int nf = 0; nf < 16; nf++) {
        const int d = h * HDIM + nf * 8 + kcol;
        float v0 = O[nf][0] * inv0, v1 = O[nf][1] * inv0;
        float v2 = O[nf][2] * inv1, v3 = O[nf][3] * inv1;
        uint32_t h0 = pack_bf2(v0, v1);
        uint32_t l0p = res_bf2(h0, v0, v1);
        uint32_t h1 = pack_bf2(v2, v3);
        uint32_t l1p = res_bf2(h1, v2, v3);
        *(uint32_t*)(g_at_hi + row0o + d) = h0;
        *(uint32_t*)(g_at_lo + row0o + d) = l0p;
        *(uint32_t*)(g_at_hi + row1o + d) = h1;
        *(uint32_t*)(g_at_lo + row1o + d) = l1p;
    }
}

// ---------------------------------------------------------------------------
extern "C" void kernel_launch(void* const* d_in, const int* in_sizes, int n_in,
                              void* d_out, int out_size) {
    const int* positions = (const int*)d_in[0];
    const float* hidden = (const float*)d_in[1];
    const float* w_qkv = (const float*)d_in[2];
    const float* q_norm_w = (const float*)d_in[3];
    const float* k_norm_w = (const float*)d_in[4];
    const float* w_o = (const float*)d_in[5];
    float* out = (float*)d_out;

    void *p_qkv, *p_hh, *p_hl, *p_qh, *p_ql, *p_oh, *p_ol, *p_ah, *p_al;
    cudaGetSymbolAddress(&p_qkv, g_qkv);
    cudaGetSymbolAddress(&p_hh, g_hid_hi);
    cudaGetSymbolAddress(&p_hl, g_hid_lo);
    cudaGetSymbolAddress(&p_qh, g_wqkv_hi);
    cudaGetSymbolAddress(&p_ql, g_wqkv_lo);
    cudaGetSymbolAddress(&p_oh, g_wo_hi);
    cudaGetSymbolAddress(&p_ol, g_wo_lo);
    cudaGetSymbolAddress(&p_ah, g_at_hi);
    cudaGetSymbolAddress(&p_al, g_at_lo);

    cudaFuncSetAttribute(gemm_bf3, cudaFuncAttributeMaxDynamicSharedMemorySize, GSMEM_BYTES);
    cudaFuncSetAttribute(attn_mma, cudaFuncAttributeMaxDynamicSharedMemorySize, ASMEM_BYTES);

    // 0) Convert GEMM operands to bf16 hi/lo
    convert_nt<<<(T_DIM * H_DIM / 4 + 255) / 256, 256>>>(
        hidden, (__nv_bfloat16*)p_hh, (__nv_bfloat16*)p_hl, T_DIM * H_DIM / 4);
    {
        dim3 g(QKV_N / 32, H_DIM / 32), b(32, 8);
        convert_t<<<g, b>>>(w_qkv, (__nv_bfloat16*)p_qh, (__nv_bfloat16*)p_ql, H_DIM, QKV_N);
    }
    {
        dim3 g(H_DIM / 32, H_DIM / 32), b(32, 8);
        convert_t<<<g, b>>>(w_o, (__nv_bfloat16*)p_oh, (__nv_bfloat16*)p_ol, H_DIM, H_DIM);
    }

    // 1) QKV projection
    {
        dim3 grid(QKV_N / 128, T_DIM / 128);
        gemm_bf3<<<grid, 256, GSMEM_BYTES>>>(
            (const __nv_bfloat16*)p_hh, (const __nv_bfloat16*)p_hl,
            (const __nv_bfloat16*)p_qh, (const __nv_bfloat16*)p_ql,
            (float*)p_qkv, T_DIM, QKV_N, H_DIM);
    }
    // 2) RMSNorm + RoPE -> bf16 hi/lo q/k/v (head-major)
    rmsnorm_rope_kernel<<<T_DIM, 256>>>(positions, q_norm_w, k_norm_w);
    // 3) Tensor-core causal flash attention -> g_at hi/lo
    {
        dim3 grid(T_DIM / AQT, NHEAD);
        attn_mma<<<grid, 256, ASMEM_BYTES>>>();
    }
    // 4) Output projection
    {
        dim3 grid(H_DIM / 128, T_DIM / 128);
        gemm_bf3<<<grid, 256, GSMEM_BYTES>>>(
            (const __nv_bfloat16*)p_ah, (const __nv_bfloat16*)p_al,
            (const __nv_bfloat16*)p_oh, (const __nv_bfloat16*)p_ol,
            out, T_DIM, H_DIM, H_DIM);
    }
}